// round 9
// baseline (speedup 1.0000x reference)
#include <cuda_runtime.h>

// AlphaGridMask: stable counting-sort by block id + trilinear grid_sample.
// N = 4,194,304 pts, 64 blocks, volume 256^3 f32 viewed as [64][64][64][64].
//
// Pass 1 (fused): per point compute bid (bit-exact), stable intra-warp rank
// (match_any + per-warp smem counters), and the trilinear sample. Store value
// + (bid,rank) in original order (coalesced). Also store per-warp bin counts
// in BOTH [b][gw] (scan input) and [gw][b] (perm preamble) layouts.
// Pass 2 (single kernel): per-bin exclusive scan across warps; the LAST CTA
// (atomic ticket) also scans the 64 bin totals into g_binbase.
// Pass 3: permutation with smem staging in CTA-bin-major order so the global
// flush is fully coalesced (dest runs of ~64 consecutive elements per bin).

#define NBIN  64
#define CTA1  256
#define NW    8            // warps per CTA
#define RND   16           // rounds per warp -> 512 points per warp
#define SEG   512
#define PPC   (NW * SEG)   // 4096 points per CTA
#define NGWMAX 8192

__device__ float          g_val[4194304];            // sampled value, orig order
__device__ unsigned short g_rank[4194304];           // (bid<<10)|rank, orig order
__device__ unsigned int   g_warpcnt[NBIN * NGWMAX];  // [b][gw] counts (scan input)
__device__ unsigned int   g_warpcnt2[NGWMAX * NBIN]; // [gw][b] counts (perm input)
__device__ unsigned int   g_warpoff[NBIN * NGWMAX];  // [b][gw] exclusive prefix
__device__ unsigned int   g_bintot[NBIN];
__device__ unsigned int   g_binbase[NBIN];
__device__ unsigned int   g_sem;                     // last-block ticket

// Bit-exact block id vs reference: IEEE sub, IEEE div, floor, clip to [0,3].
__device__ __forceinline__ int bid_of(float x, float y, float z,
                                      float a0x, float a0y, float a0z,
                                      float vx, float vy, float vz) {
    float qx = __fdiv_rn(x - a0x, vx);
    float qy = __fdiv_rn(y - a0y, vy);
    float qz = __fdiv_rn(z - a0z, vz);
    int ix = (int)floorf(qx);
    int iy = (int)floorf(qy);
    int iz = (int)floorf(qz);
    ix = min(max(ix, 0), 3);
    iy = min(max(iy, 0), 3);
    iz = min(max(iz, 0), 3);
    return (ix << 4) + (iy << 2) + iz;   // strides [16,4,1]
}

__device__ __forceinline__ float sel4(float4 V, int s) {
    return (s == 0) ? V.x : ((s == 1) ? V.y : ((s == 2) ? V.z : V.w));
}

// ---------------- Pass 1 (fused): bid + rank + trilinear sample --------------
__global__ void __launch_bounds__(CTA1, 6) k_fused(const float* __restrict__ xyz,
                                                   const float* __restrict__ aabb,
                                                   const float* __restrict__ vol,
                                                   const float* __restrict__ dmin,
                                                   const float* __restrict__ dmax,
                                                   int ngw) {
    __shared__ unsigned int cnt[NW * NBIN];
    __shared__ float s_bb[6];
    __shared__ float s_org[NBIN * 3];
    __shared__ float s_scl[NBIN * 3];
    int tid = threadIdx.x, w = tid >> 5, lane = tid & 31;
    cnt[tid] = 0;
    cnt[tid + 256] = 0;
    if (tid < 6) s_bb[tid] = aabb[tid];
    if (blockIdx.x == 0 && tid == 0) g_sem = 0;      // reset ticket each launch
    for (int i = tid; i < NBIN * 3; i += CTA1) {
        float dn = dmin[i];
        s_org[i] = dn;
        s_scl[i] = 63.0f / (dmax[i] - dn);   // f = (p-dmin)*63/(dmax-dmin)
    }
    __syncthreads();

    float a0x = s_bb[0], a0y = s_bb[1], a0z = s_bb[2];
    float vx = (s_bb[3] - a0x) * 0.25f;      // /4 exact
    float vy = (s_bb[4] - a0y) * 0.25f;
    float vz = (s_bb[5] - a0z) * 0.25f;

    int gw = blockIdx.x * NW + w;
    size_t segbase = (size_t)gw * SEG;
    unsigned int lmlt = (1u << lane) - 1u;
    unsigned int* mycnt = cnt + w * NBIN;

    #pragma unroll 2
    for (int r = 0; r < RND; r++) {
        size_t p = segbase + (size_t)r * 32 + lane;
        const float* q = xyz + p * 3;
        float x = __ldcs(q + 0), y = __ldcs(q + 1), z = __ldcs(q + 2);
        int bid = bid_of(x, y, z, a0x, a0y, a0z, vx, vy, vz);

        // ---- stable rank via match (serial chain overlaps gather latency) ----
        unsigned int mask = __match_any_sync(0xffffffffu, bid);
        int leader = __ffs(mask) - 1;
        unsigned int base = 0;
        if (lane == leader) base = mycnt[bid];
        base = __shfl_sync(0xffffffffu, base, leader);
        unsigned int rank = base + __popc(mask & lmlt);
        if (lane == leader) mycnt[bid] = base + __popc(mask);
        g_rank[p] = (unsigned short)(((unsigned)bid << 10) | rank);

        // ---- trilinear sample (independent work) ----
        int b3 = bid * 3;
        float fx = (x - s_org[b3 + 0]) * s_scl[b3 + 0];
        float fy = (y - s_org[b3 + 1]) * s_scl[b3 + 1];
        float fz = (z - s_org[b3 + 2]) * s_scl[b3 + 2];
        float x0f = floorf(fx), y0f = floorf(fy), z0f = floorf(fz);
        float wx = fx - x0f, wy = fy - y0f, wzt = fz - z0f;
        int x0 = (int)x0f, y0 = (int)y0f, z0 = (int)z0f;
        int x0c = min(max(x0, 0), 63), x1c = min(max(x0 + 1, 0), 63);
        int y0c = min(max(y0, 0), 63), y1c = min(max(y0 + 1, 0), 63);
        int z0c = min(max(z0, 0), 63), z1c = min(max(z0 + 1, 0), 63);

        const float* vb = vol + ((size_t)bid << 18);
        int zy00 = ((z0c << 6) + y0c) << 6;
        int zy01 = ((z0c << 6) + y1c) << 6;
        int zy10 = ((z1c << 6) + y0c) << 6;
        int zy11 = ((z1c << 6) + y1c) << 6;

        int xb = x0c & ~3;                   // 16B-aligned base covering x0
        int s  = x0c & 3;

        float4 V00 = __ldg((const float4*)(vb + zy00 + xb));
        float4 V01 = __ldg((const float4*)(vb + zy01 + xb));
        float4 V10 = __ldg((const float4*)(vb + zy10 + xb));
        float4 V11 = __ldg((const float4*)(vb + zy11 + xb));

        float v000 = sel4(V00, s), v010 = sel4(V01, s);
        float v100 = sel4(V10, s), v110 = sel4(V11, s);
        float v001, v011, v101, v111;
        if (s < 3) {
            v001 = sel4(V00, s + 1);
            v011 = sel4(V01, s + 1);
            v101 = sel4(V10, s + 1);
            v111 = sel4(V11, s + 1);
        } else {                             // x0c%4==3: neighbor in next float4
            v001 = __ldg(vb + zy00 + x1c);
            v011 = __ldg(vb + zy01 + x1c);
            v101 = __ldg(vb + zy10 + x1c);
            v111 = __ldg(vb + zy11 + x1c);
        }

        float omx = 1.0f - wx, omy = 1.0f - wy, omz = 1.0f - wzt;
        float res = omz * (omy * (omx * v000 + wx * v001) + wy * (omx * v010 + wx * v011))
                  + wzt * (omy * (omx * v100 + wx * v101) + wy * (omx * v110 + wx * v111));
        g_val[p] = res;
        __syncwarp();
    }

    // per-warp bin totals, both layouts
    g_warpcnt[(size_t)lane * ngw + gw]        = mycnt[lane];
    g_warpcnt[(size_t)(lane + 32) * ngw + gw] = mycnt[lane + 32];
    g_warpcnt2[(size_t)gw * NBIN + lane]      = mycnt[lane];
    g_warpcnt2[(size_t)gw * NBIN + 32 + lane] = mycnt[lane + 32];
}

// ------- Pass 2: per-bin scan across warps; last CTA scans bin totals -------
__global__ void __launch_bounds__(256) k_scan_gw(int ngw) {
    int b = blockIdx.x, tid = threadIdx.x;
    const unsigned int* row = g_warpcnt + (size_t)b * ngw;
    unsigned int* orow = g_warpoff + (size_t)b * ngw;
    int per = (ngw + 255) >> 8;
    int base = tid * per;
    unsigned int s = 0;
    for (int k = 0; k < per; k++) { int i = base + k; if (i < ngw) s += row[i]; }
    __shared__ unsigned int sh[256];
    sh[tid] = s;
    __syncthreads();
    #pragma unroll
    for (int off = 1; off < 256; off <<= 1) {
        unsigned int v = (tid >= off) ? sh[tid - off] : 0;
        __syncthreads();
        if (tid >= off) sh[tid] += v;
        __syncthreads();
    }
    unsigned int incl = sh[tid];
    if (tid == 255) g_bintot[b] = incl;
    unsigned int run = incl - s;
    for (int k = 0; k < per; k++) {
        int i = base + k;
        if (i < ngw) { unsigned int v = row[i]; orow[i] = run; run += v; }
    }

    // last CTA computes g_binbase from g_bintot
    __shared__ unsigned int isLast;
    __threadfence();
    if (tid == 0) isLast = (atomicAdd(&g_sem, 1u) == NBIN - 1) ? 1u : 0u;
    __syncthreads();
    if (isLast) {
        __shared__ unsigned int bt[NBIN];
        if (tid < NBIN) bt[tid] = g_bintot[tid];
        __syncthreads();
        for (int off = 1; off < NBIN; off <<= 1) {
            unsigned int u = 0;
            if (tid < NBIN && tid >= off) u = bt[tid - off];
            __syncthreads();
            if (tid < NBIN && tid >= off) bt[tid] += u;
            __syncthreads();
        }
        if (tid < NBIN) g_binbase[tid] = bt[tid] - g_bintot[tid];
    }
}

// -------- Pass 3: permutation with CTA-bin-major smem staging ---------------
__global__ void __launch_bounds__(CTA1) k_perm(float* __restrict__ out, int ngw) {
    __shared__ float          s_val[PPC];            // 16KB staged values
    __shared__ unsigned short s_bin[PPC];            // 8KB  bin per slot
    __shared__ unsigned short s_cnt[NW * NBIN];      // counts [w][b]
    __shared__ unsigned short s_ls[NW * NBIN];       // slot start per (warp,bin)
    __shared__ unsigned short s_cs[NBIN];            // CTA-local bin start
    __shared__ unsigned int   s_db[NBIN];            // global dest base per bin
    __shared__ unsigned int   s_T[NBIN];
    int tid = threadIdx.x, w = tid >> 5, lane = tid & 31;
    int gw0 = blockIdx.x * NW;

    // counts, coalesced from [gw][b] layout (s_cnt[w][b] == g_warpcnt2[gw0+w][b])
    for (int i = tid; i < NW * NBIN; i += CTA1)
        s_cnt[i] = (unsigned short)g_warpcnt2[(size_t)gw0 * NBIN + i];
    __syncthreads();

    if (tid < NBIN) {
        unsigned int t = 0;
        #pragma unroll
        for (int w2 = 0; w2 < NW; w2++) t += s_cnt[w2 * NBIN + tid];
        s_T[tid] = t;
    }
    __syncthreads();
    // inclusive scan of s_T over 64 bins (Hillis-Steele, full-block barriers)
    for (int off = 1; off < NBIN; off <<= 1) {
        unsigned int u = 0;
        if (tid < NBIN && tid >= off) u = s_T[tid - off];
        __syncthreads();
        if (tid < NBIN && tid >= off) s_T[tid] += u;
        __syncthreads();
    }
    if (tid < NBIN) {
        unsigned int own = 0;
        #pragma unroll
        for (int w2 = 0; w2 < NW; w2++) own += s_cnt[w2 * NBIN + tid];
        unsigned int cs = s_T[tid] - own;            // exclusive CTA-local start
        s_cs[tid] = (unsigned short)cs;
        unsigned int run = cs;
        #pragma unroll
        for (int w2 = 0; w2 < NW; w2++) {
            s_ls[w2 * NBIN + tid] = (unsigned short)run;
            run += s_cnt[w2 * NBIN + tid];
        }
        s_db[tid] = g_binbase[tid] + g_warpoff[(size_t)tid * ngw + gw0];
    }
    __syncthreads();

    // stage: slot = ls[w][bid] + rank  (CTA-bin-major order)
    const unsigned short* ls = s_ls + w * NBIN;
    size_t segbase = (size_t)(gw0 + w) * SEG;
    #pragma unroll
    for (int r = 0; r < RND; r++) {
        size_t p = segbase + (size_t)r * 32 + lane;
        unsigned int pk = __ldcs(g_rank + p);
        float v = __ldcs(g_val + p);
        int b = pk >> 10;
        unsigned int slot = (unsigned int)ls[b] + (pk & 1023u);
        s_val[slot] = v;
        s_bin[slot] = (unsigned short)b;
    }
    __syncthreads();

    // flush: consecutive slots -> consecutive global dests (runs of ~64)
    #pragma unroll
    for (int s0 = 0; s0 < PPC; s0 += CTA1) {
        int s = s0 + tid;
        int b = s_bin[s];
        unsigned int dest = s_db[b] + (unsigned int)(s - (int)s_cs[b]);
        __stcs(out + dest, s_val[s]);
    }
}

extern "C" void kernel_launch(void* const* d_in, const int* in_sizes, int n_in,
                              void* d_out, int out_size) {
    const float* xyz  = (const float*)d_in[0];
    const float* aabb = (const float*)d_in[1];
    const float* vol  = (const float*)d_in[2];
    const float* dmin = (const float*)d_in[3];
    const float* dmax = (const float*)d_in[4];
    float* out = (float*)d_out;

    int n   = in_sizes[0] / 3;      // 4,194,304
    int ngw = n / SEG;              // 8192 warps
    int ncta = ngw / NW;            // 1024 CTAs

    k_fused<<<ncta, CTA1>>>(xyz, aabb, vol, dmin, dmax, ngw);
    k_scan_gw<<<NBIN, 256>>>(ngw);
    k_perm<<<ncta, CTA1>>>(out, ngw);
}

// round 10
// speedup vs baseline: 1.0682x; 1.0682x over previous
#include <cuda_runtime.h>

// AlphaGridMask: stable counting-sort by block id + trilinear grid_sample.
// N = 4,194,304 pts, 64 blocks, volume 256^3 f32 viewed as [64][64][64][64].
//
// Pass 1 (fused): per point compute bid (bit-exact), stable intra-warp rank
// (match_any + per-warp smem counters), and the trilinear sample. Store value
// + (bid,rank) in original order (coalesced). Also store per-warp bin counts
// in BOTH [b][gw] (scan input) and [gw][b] (perm preamble) layouts.
// Pass 2 (single kernel): per-bin exclusive scan across warps; the LAST CTA
// (atomic ticket) also scans the 64 bin totals into g_binbase.
// Pass 3: permutation with smem staging in CTA-bin-major order so the global
// flush is fully coalesced (dest runs of ~64 consecutive elements per bin).

#define NBIN  64
#define CTA1  256
#define NW    8            // warps per CTA
#define RND   16           // rounds per warp -> 512 points per warp
#define SEG   512
#define PPC   (NW * SEG)   // 4096 points per CTA
#define NGWMAX 8192

__device__ float          g_val[4194304];            // sampled value, orig order
__device__ unsigned short g_rank[4194304];           // (bid<<10)|rank, orig order
__device__ unsigned int   g_warpcnt[NBIN * NGWMAX];  // [b][gw] counts (scan input)
__device__ unsigned int   g_warpcnt2[NGWMAX * NBIN]; // [gw][b] counts (perm input)
__device__ unsigned int   g_warpoff[NBIN * NGWMAX];  // [b][gw] exclusive prefix
__device__ unsigned int   g_bintot[NBIN];
__device__ unsigned int   g_binbase[NBIN];
__device__ unsigned int   g_sem;                     // last-block ticket

// Bit-exact block id vs reference: IEEE sub, IEEE div, floor, clip to [0,3].
__device__ __forceinline__ int bid_of(float x, float y, float z,
                                      float a0x, float a0y, float a0z,
                                      float vx, float vy, float vz) {
    float qx = __fdiv_rn(x - a0x, vx);
    float qy = __fdiv_rn(y - a0y, vy);
    float qz = __fdiv_rn(z - a0z, vz);
    int ix = (int)floorf(qx);
    int iy = (int)floorf(qy);
    int iz = (int)floorf(qz);
    ix = min(max(ix, 0), 3);
    iy = min(max(iy, 0), 3);
    iz = min(max(iz, 0), 3);
    return (ix << 4) + (iy << 2) + iz;   // strides [16,4,1]
}

__device__ __forceinline__ float sel4(float4 V, int s) {
    return (s == 0) ? V.x : ((s == 1) ? V.y : ((s == 2) ? V.z : V.w));
}

// ---------------- Pass 1 (fused): bid + rank + trilinear sample --------------
__global__ void __launch_bounds__(CTA1) k_fused(const float* __restrict__ xyz,
                                                const float* __restrict__ aabb,
                                                const float* __restrict__ vol,
                                                const float* __restrict__ dmin,
                                                const float* __restrict__ dmax,
                                                int ngw) {
    __shared__ unsigned int cnt[NW * NBIN];
    __shared__ float s_bb[6];
    __shared__ float s_org[NBIN * 3];
    __shared__ float s_scl[NBIN * 3];
    int tid = threadIdx.x, w = tid >> 5, lane = tid & 31;
    cnt[tid] = 0;
    cnt[tid + 256] = 0;
    if (tid < 6) s_bb[tid] = aabb[tid];
    if (blockIdx.x == 0 && tid == 0) g_sem = 0;      // reset ticket each launch
    for (int i = tid; i < NBIN * 3; i += CTA1) {
        float dn = dmin[i];
        s_org[i] = dn;
        s_scl[i] = 63.0f / (dmax[i] - dn);   // f = (p-dmin)*63/(dmax-dmin)
    }
    __syncthreads();

    float a0x = s_bb[0], a0y = s_bb[1], a0z = s_bb[2];
    float vx = (s_bb[3] - a0x) * 0.25f;      // /4 exact
    float vy = (s_bb[4] - a0y) * 0.25f;
    float vz = (s_bb[5] - a0z) * 0.25f;

    int gw = blockIdx.x * NW + w;
    size_t segbase = (size_t)gw * SEG;
    unsigned int lmlt = (1u << lane) - 1u;
    unsigned int* mycnt = cnt + w * NBIN;

    #pragma unroll 2
    for (int r = 0; r < RND; r++) {
        size_t p = segbase + (size_t)r * 32 + lane;
        const float* q = xyz + p * 3;
        float x = __ldcs(q + 0), y = __ldcs(q + 1), z = __ldcs(q + 2);
        int bid = bid_of(x, y, z, a0x, a0y, a0z, vx, vy, vz);

        // ---- stable rank via match (serial chain overlaps gather latency) ----
        unsigned int mask = __match_any_sync(0xffffffffu, bid);
        int leader = __ffs(mask) - 1;
        unsigned int base = 0;
        if (lane == leader) base = mycnt[bid];
        base = __shfl_sync(0xffffffffu, base, leader);
        unsigned int rank = base + __popc(mask & lmlt);
        if (lane == leader) mycnt[bid] = base + __popc(mask);
        g_rank[p] = (unsigned short)(((unsigned)bid << 10) | rank);

        // ---- trilinear sample (independent work) ----
        int b3 = bid * 3;
        float fx = (x - s_org[b3 + 0]) * s_scl[b3 + 0];
        float fy = (y - s_org[b3 + 1]) * s_scl[b3 + 1];
        float fz = (z - s_org[b3 + 2]) * s_scl[b3 + 2];
        float x0f = floorf(fx), y0f = floorf(fy), z0f = floorf(fz);
        float wx = fx - x0f, wy = fy - y0f, wzt = fz - z0f;
        int x0 = (int)x0f, y0 = (int)y0f, z0 = (int)z0f;
        int x0c = min(max(x0, 0), 63), x1c = min(max(x0 + 1, 0), 63);
        int y0c = min(max(y0, 0), 63), y1c = min(max(y0 + 1, 0), 63);
        int z0c = min(max(z0, 0), 63), z1c = min(max(z0 + 1, 0), 63);

        const float* vb = vol + ((size_t)bid << 18);
        int zy00 = ((z0c << 6) + y0c) << 6;
        int zy01 = ((z0c << 6) + y1c) << 6;
        int zy10 = ((z1c << 6) + y0c) << 6;
        int zy11 = ((z1c << 6) + y1c) << 6;

        int xb = x0c & ~3;                   // 16B-aligned base covering x0
        int s  = x0c & 3;

        float4 V00 = __ldg((const float4*)(vb + zy00 + xb));
        float4 V01 = __ldg((const float4*)(vb + zy01 + xb));
        float4 V10 = __ldg((const float4*)(vb + zy10 + xb));
        float4 V11 = __ldg((const float4*)(vb + zy11 + xb));

        float v000 = sel4(V00, s), v010 = sel4(V01, s);
        float v100 = sel4(V10, s), v110 = sel4(V11, s);
        float v001, v011, v101, v111;
        if (s < 3) {
            v001 = sel4(V00, s + 1);
            v011 = sel4(V01, s + 1);
            v101 = sel4(V10, s + 1);
            v111 = sel4(V11, s + 1);
        } else {                             // x0c%4==3: neighbor in next float4
            v001 = __ldg(vb + zy00 + x1c);
            v011 = __ldg(vb + zy01 + x1c);
            v101 = __ldg(vb + zy10 + x1c);
            v111 = __ldg(vb + zy11 + x1c);
        }

        float omx = 1.0f - wx, omy = 1.0f - wy, omz = 1.0f - wzt;
        float res = omz * (omy * (omx * v000 + wx * v001) + wy * (omx * v010 + wx * v011))
                  + wzt * (omy * (omx * v100 + wx * v101) + wy * (omx * v110 + wx * v111));
        g_val[p] = res;
        __syncwarp();
    }

    // per-warp bin totals, both layouts
    g_warpcnt[(size_t)lane * ngw + gw]        = mycnt[lane];
    g_warpcnt[(size_t)(lane + 32) * ngw + gw] = mycnt[lane + 32];
    g_warpcnt2[(size_t)gw * NBIN + lane]      = mycnt[lane];
    g_warpcnt2[(size_t)gw * NBIN + 32 + lane] = mycnt[lane + 32];
}

// ------- Pass 2: per-bin scan across warps; last CTA scans bin totals -------
__global__ void __launch_bounds__(256) k_scan_gw(int ngw) {
    int b = blockIdx.x, tid = threadIdx.x;
    const unsigned int* row = g_warpcnt + (size_t)b * ngw;
    unsigned int* orow = g_warpoff + (size_t)b * ngw;
    int per = (ngw + 255) >> 8;
    int base = tid * per;
    unsigned int s = 0;
    for (int k = 0; k < per; k++) { int i = base + k; if (i < ngw) s += row[i]; }
    __shared__ unsigned int sh[256];
    sh[tid] = s;
    __syncthreads();
    #pragma unroll
    for (int off = 1; off < 256; off <<= 1) {
        unsigned int v = (tid >= off) ? sh[tid - off] : 0;
        __syncthreads();
        if (tid >= off) sh[tid] += v;
        __syncthreads();
    }
    unsigned int incl = sh[tid];
    if (tid == 255) g_bintot[b] = incl;
    unsigned int run = incl - s;
    for (int k = 0; k < per; k++) {
        int i = base + k;
        if (i < ngw) { unsigned int v = row[i]; orow[i] = run; run += v; }
    }

    // last CTA computes g_binbase from g_bintot
    __shared__ unsigned int isLast;
    __threadfence();
    if (tid == 0) isLast = (atomicAdd(&g_sem, 1u) == NBIN - 1) ? 1u : 0u;
    __syncthreads();
    if (isLast) {
        __shared__ unsigned int bt[NBIN];
        if (tid < NBIN) bt[tid] = g_bintot[tid];
        __syncthreads();
        for (int off = 1; off < NBIN; off <<= 1) {
            unsigned int u = 0;
            if (tid < NBIN && tid >= off) u = bt[tid - off];
            __syncthreads();
            if (tid < NBIN && tid >= off) bt[tid] += u;
            __syncthreads();
        }
        if (tid < NBIN) g_binbase[tid] = bt[tid] - g_bintot[tid];
    }
}

// -------- Pass 3: permutation with CTA-bin-major smem staging ---------------
__global__ void __launch_bounds__(CTA1) k_perm(float* __restrict__ out, int ngw) {
    __shared__ float          s_val[PPC];            // 16KB staged values
    __shared__ unsigned short s_bin[PPC];            // 8KB  bin per slot
    __shared__ unsigned short s_cnt[NW * NBIN];      // counts [w][b]
    __shared__ unsigned short s_ls[NW * NBIN];       // slot start per (warp,bin)
    __shared__ unsigned short s_cs[NBIN];            // CTA-local bin start
    __shared__ unsigned int   s_db[NBIN];            // global dest base per bin
    __shared__ unsigned int   s_T[NBIN];
    int tid = threadIdx.x, w = tid >> 5, lane = tid & 31;
    int gw0 = blockIdx.x * NW;

    // counts, coalesced from [gw][b] layout (s_cnt[w][b] == g_warpcnt2[gw0+w][b])
    for (int i = tid; i < NW * NBIN; i += CTA1)
        s_cnt[i] = (unsigned short)g_warpcnt2[(size_t)gw0 * NBIN + i];
    __syncthreads();

    if (tid < NBIN) {
        unsigned int t = 0;
        #pragma unroll
        for (int w2 = 0; w2 < NW; w2++) t += s_cnt[w2 * NBIN + tid];
        s_T[tid] = t;
    }
    __syncthreads();
    // inclusive scan of s_T over 64 bins (Hillis-Steele, full-block barriers)
    for (int off = 1; off < NBIN; off <<= 1) {
        unsigned int u = 0;
        if (tid < NBIN && tid >= off) u = s_T[tid - off];
        __syncthreads();
        if (tid < NBIN && tid >= off) s_T[tid] += u;
        __syncthreads();
    }
    if (tid < NBIN) {
        unsigned int own = 0;
        #pragma unroll
        for (int w2 = 0; w2 < NW; w2++) own += s_cnt[w2 * NBIN + tid];
        unsigned int cs = s_T[tid] - own;            // exclusive CTA-local start
        s_cs[tid] = (unsigned short)cs;
        unsigned int run = cs;
        #pragma unroll
        for (int w2 = 0; w2 < NW; w2++) {
            s_ls[w2 * NBIN + tid] = (unsigned short)run;
            run += s_cnt[w2 * NBIN + tid];
        }
        s_db[tid] = g_binbase[tid] + g_warpoff[(size_t)tid * ngw + gw0];
    }
    __syncthreads();

    // stage: slot = ls[w][bid] + rank  (CTA-bin-major order)
    const unsigned short* ls = s_ls + w * NBIN;
    size_t segbase = (size_t)(gw0 + w) * SEG;
    #pragma unroll
    for (int r = 0; r < RND; r++) {
        size_t p = segbase + (size_t)r * 32 + lane;
        unsigned int pk = __ldcs(g_rank + p);
        float v = __ldcs(g_val + p);
        int b = pk >> 10;
        unsigned int slot = (unsigned int)ls[b] + (pk & 1023u);
        s_val[slot] = v;
        s_bin[slot] = (unsigned short)b;
    }
    __syncthreads();

    // flush: consecutive slots -> consecutive global dests (runs of ~64)
    #pragma unroll
    for (int s0 = 0; s0 < PPC; s0 += CTA1) {
        int s = s0 + tid;
        int b = s_bin[s];
        unsigned int dest = s_db[b] + (unsigned int)(s - (int)s_cs[b]);
        __stcs(out + dest, s_val[s]);
    }
}

extern "C" void kernel_launch(void* const* d_in, const int* in_sizes, int n_in,
                              void* d_out, int out_size) {
    const float* xyz  = (const float*)d_in[0];
    const float* aabb = (const float*)d_in[1];
    const float* vol  = (const float*)d_in[2];
    const float* dmin = (const float*)d_in[3];
    const float* dmax = (const float*)d_in[4];
    float* out = (float*)d_out;

    int n   = in_sizes[0] / 3;      // 4,194,304
    int ngw = n / SEG;              // 8192 warps
    int ncta = ngw / NW;            // 1024 CTAs

    k_fused<<<ncta, CTA1>>>(xyz, aabb, vol, dmin, dmax, ngw);
    k_scan_gw<<<NBIN, 256>>>(ngw);
    k_perm<<<ncta, CTA1>>>(out, ngw);
}

// round 11
// speedup vs baseline: 1.1377x; 1.0650x over previous
#include <cuda_runtime.h>

// AlphaGridMask: stable counting-sort by block id + trilinear grid_sample.
// N = 4,194,304 pts, 64 blocks, volume 256^3 f32 viewed as [64][64][64][64].
//
// Pass 1 (fused): per point compute bid (bit-exact), stable intra-warp rank
// (match_any + per-warp smem counters), and the trilinear sample. Store value
// + (bid,rank) in original order (coalesced). Also store per-warp bin counts
// in BOTH [b][gw] (scan input) and [gw][b] (perm preamble) layouts.
// Pass 2 (single kernel): per-bin exclusive scan across warps; the LAST CTA
// (atomic ticket) also scans the 64 bin totals into g_binbase.
// Pass 3: permutation with smem staging in CTA-bin-major order so the global
// flush is fully coalesced (dest runs of ~64 consecutive elements per bin).

#define NBIN  64
#define CTA1  256
#define NW    8            // warps per CTA
#define RND   16           // rounds per warp -> 512 points per warp
#define SEG   512
#define PPC   (NW * SEG)   // 4096 points per CTA
#define NGWMAX 8192

__device__ float          g_val[4194304];            // sampled value, orig order
__device__ unsigned short g_rank[4194304];           // (bid<<10)|rank, orig order
__device__ unsigned int   g_warpcnt[NBIN * NGWMAX];  // [b][gw] counts (scan input)
__device__ unsigned int   g_warpcnt2[NGWMAX * NBIN]; // [gw][b] counts (perm input)
__device__ unsigned int   g_warpoff[NBIN * NGWMAX];  // [b][gw] exclusive prefix
__device__ unsigned int   g_bintot[NBIN];
__device__ unsigned int   g_binbase[NBIN];
__device__ unsigned int   g_sem;                     // last-block ticket

// Bit-exact block id vs reference: IEEE sub, IEEE div, floor, clip to [0,3].
__device__ __forceinline__ int bid_of(float x, float y, float z,
                                      float a0x, float a0y, float a0z,
                                      float vx, float vy, float vz) {
    float qx = __fdiv_rn(x - a0x, vx);
    float qy = __fdiv_rn(y - a0y, vy);
    float qz = __fdiv_rn(z - a0z, vz);
    int ix = (int)floorf(qx);
    int iy = (int)floorf(qy);
    int iz = (int)floorf(qz);
    ix = min(max(ix, 0), 3);
    iy = min(max(iy, 0), 3);
    iz = min(max(iz, 0), 3);
    return (ix << 4) + (iy << 2) + iz;   // strides [16,4,1]
}

__device__ __forceinline__ float sel4(float4 V, int s) {
    return (s == 0) ? V.x : ((s == 1) ? V.y : ((s == 2) ? V.z : V.w));
}

// ---------------- Pass 1 (fused): bid + rank + trilinear sample --------------
__global__ void __launch_bounds__(CTA1) k_fused(const float* __restrict__ xyz,
                                                const float* __restrict__ aabb,
                                                const float* __restrict__ vol,
                                                const float* __restrict__ dmin,
                                                const float* __restrict__ dmax,
                                                int ngw) {
    __shared__ unsigned int cnt[NW * NBIN];
    __shared__ float s_bb[6];
    __shared__ float s_org[NBIN * 3];
    __shared__ float s_scl[NBIN * 3];
    int tid = threadIdx.x, w = tid >> 5, lane = tid & 31;
    cnt[tid] = 0;
    cnt[tid + 256] = 0;
    if (tid < 6) s_bb[tid] = aabb[tid];
    if (blockIdx.x == 0 && tid == 0) g_sem = 0;      // reset ticket each launch
    for (int i = tid; i < NBIN * 3; i += CTA1) {
        float dn = dmin[i];
        s_org[i] = dn;
        s_scl[i] = 63.0f / (dmax[i] - dn);   // f = (p-dmin)*63/(dmax-dmin)
    }
    __syncthreads();

    float a0x = s_bb[0], a0y = s_bb[1], a0z = s_bb[2];
    float vx = (s_bb[3] - a0x) * 0.25f;      // /4 exact
    float vy = (s_bb[4] - a0y) * 0.25f;
    float vz = (s_bb[5] - a0z) * 0.25f;

    int gw = blockIdx.x * NW + w;
    size_t segbase = (size_t)gw * SEG;
    unsigned int lmlt = (1u << lane) - 1u;
    unsigned int* mycnt = cnt + w * NBIN;

    #pragma unroll 4
    for (int r = 0; r < RND; r++) {
        size_t p = segbase + (size_t)r * 32 + lane;
        const float* q = xyz + p * 3;
        float x = __ldcs(q + 0), y = __ldcs(q + 1), z = __ldcs(q + 2);
        int bid = bid_of(x, y, z, a0x, a0y, a0z, vx, vy, vz);

        // ---- stable rank via match (serial chain overlaps gather latency) ----
        unsigned int mask = __match_any_sync(0xffffffffu, bid);
        int leader = __ffs(mask) - 1;
        unsigned int base = 0;
        if (lane == leader) base = mycnt[bid];
        base = __shfl_sync(0xffffffffu, base, leader);
        unsigned int rank = base + __popc(mask & lmlt);
        if (lane == leader) mycnt[bid] = base + __popc(mask);
        g_rank[p] = (unsigned short)(((unsigned)bid << 10) | rank);

        // ---- trilinear sample (independent work) ----
        int b3 = bid * 3;
        float fx = (x - s_org[b3 + 0]) * s_scl[b3 + 0];
        float fy = (y - s_org[b3 + 1]) * s_scl[b3 + 1];
        float fz = (z - s_org[b3 + 2]) * s_scl[b3 + 2];
        float x0f = floorf(fx), y0f = floorf(fy), z0f = floorf(fz);
        float wx = fx - x0f, wy = fy - y0f, wzt = fz - z0f;
        int x0 = (int)x0f, y0 = (int)y0f, z0 = (int)z0f;
        int x0c = min(max(x0, 0), 63), x1c = min(max(x0 + 1, 0), 63);
        int y0c = min(max(y0, 0), 63), y1c = min(max(y0 + 1, 0), 63);
        int z0c = min(max(z0, 0), 63), z1c = min(max(z0 + 1, 0), 63);

        const float* vb = vol + ((size_t)bid << 18);
        int zy00 = ((z0c << 6) + y0c) << 6;
        int zy01 = ((z0c << 6) + y1c) << 6;
        int zy10 = ((z1c << 6) + y0c) << 6;
        int zy11 = ((z1c << 6) + y1c) << 6;

        int xb = x0c & ~3;                   // 16B-aligned base covering x0
        int s  = x0c & 3;

        float4 V00 = __ldg((const float4*)(vb + zy00 + xb));
        float4 V01 = __ldg((const float4*)(vb + zy01 + xb));
        float4 V10 = __ldg((const float4*)(vb + zy10 + xb));
        float4 V11 = __ldg((const float4*)(vb + zy11 + xb));

        float v000 = sel4(V00, s), v010 = sel4(V01, s);
        float v100 = sel4(V10, s), v110 = sel4(V11, s);
        float v001, v011, v101, v111;
        if (s < 3) {
            v001 = sel4(V00, s + 1);
            v011 = sel4(V01, s + 1);
            v101 = sel4(V10, s + 1);
            v111 = sel4(V11, s + 1);
        } else {                             // x0c%4==3: neighbor in next float4
            v001 = __ldg(vb + zy00 + x1c);
            v011 = __ldg(vb + zy01 + x1c);
            v101 = __ldg(vb + zy10 + x1c);
            v111 = __ldg(vb + zy11 + x1c);
        }

        float omx = 1.0f - wx, omy = 1.0f - wy, omz = 1.0f - wzt;
        float res = omz * (omy * (omx * v000 + wx * v001) + wy * (omx * v010 + wx * v011))
                  + wzt * (omy * (omx * v100 + wx * v101) + wy * (omx * v110 + wx * v111));
        g_val[p] = res;
        __syncwarp();
    }

    // per-warp bin totals, both layouts
    g_warpcnt[(size_t)lane * ngw + gw]        = mycnt[lane];
    g_warpcnt[(size_t)(lane + 32) * ngw + gw] = mycnt[lane + 32];
    g_warpcnt2[(size_t)gw * NBIN + lane]      = mycnt[lane];
    g_warpcnt2[(size_t)gw * NBIN + 32 + lane] = mycnt[lane + 32];
}

// ------- Pass 2: per-bin scan across warps; last CTA scans bin totals -------
__global__ void __launch_bounds__(256) k_scan_gw(int ngw) {
    int b = blockIdx.x, tid = threadIdx.x;
    const unsigned int* row = g_warpcnt + (size_t)b * ngw;
    unsigned int* orow = g_warpoff + (size_t)b * ngw;
    int per = (ngw + 255) >> 8;
    int base = tid * per;
    unsigned int s = 0;
    for (int k = 0; k < per; k++) { int i = base + k; if (i < ngw) s += row[i]; }
    __shared__ unsigned int sh[256];
    sh[tid] = s;
    __syncthreads();
    #pragma unroll
    for (int off = 1; off < 256; off <<= 1) {
        unsigned int v = (tid >= off) ? sh[tid - off] : 0;
        __syncthreads();
        if (tid >= off) sh[tid] += v;
        __syncthreads();
    }
    unsigned int incl = sh[tid];
    if (tid == 255) g_bintot[b] = incl;
    unsigned int run = incl - s;
    for (int k = 0; k < per; k++) {
        int i = base + k;
        if (i < ngw) { unsigned int v = row[i]; orow[i] = run; run += v; }
    }

    // last CTA computes g_binbase from g_bintot
    __shared__ unsigned int isLast;
    __threadfence();
    if (tid == 0) isLast = (atomicAdd(&g_sem, 1u) == NBIN - 1) ? 1u : 0u;
    __syncthreads();
    if (isLast) {
        __shared__ unsigned int bt[NBIN];
        if (tid < NBIN) bt[tid] = g_bintot[tid];
        __syncthreads();
        for (int off = 1; off < NBIN; off <<= 1) {
            unsigned int u = 0;
            if (tid < NBIN && tid >= off) u = bt[tid - off];
            __syncthreads();
            if (tid < NBIN && tid >= off) bt[tid] += u;
            __syncthreads();
        }
        if (tid < NBIN) g_binbase[tid] = bt[tid] - g_bintot[tid];
    }
}

// -------- Pass 3: permutation with CTA-bin-major smem staging ---------------
__global__ void __launch_bounds__(CTA1) k_perm(float* __restrict__ out, int ngw) {
    __shared__ float          s_val[PPC];            // 16KB staged values
    __shared__ unsigned short s_bin[PPC];            // 8KB  bin per slot
    __shared__ unsigned short s_cnt[NW * NBIN];      // counts [w][b]
    __shared__ unsigned short s_ls[NW * NBIN];       // slot start per (warp,bin)
    __shared__ unsigned short s_cs[NBIN];            // CTA-local bin start
    __shared__ unsigned int   s_db[NBIN];            // global dest base per bin
    __shared__ unsigned int   s_T[NBIN];
    int tid = threadIdx.x, w = tid >> 5, lane = tid & 31;
    int gw0 = blockIdx.x * NW;

    // counts, coalesced from [gw][b] layout (s_cnt[w][b] == g_warpcnt2[gw0+w][b])
    for (int i = tid; i < NW * NBIN; i += CTA1)
        s_cnt[i] = (unsigned short)g_warpcnt2[(size_t)gw0 * NBIN + i];
    __syncthreads();

    if (tid < NBIN) {
        unsigned int t = 0;
        #pragma unroll
        for (int w2 = 0; w2 < NW; w2++) t += s_cnt[w2 * NBIN + tid];
        s_T[tid] = t;
    }
    __syncthreads();
    // inclusive scan of s_T over 64 bins (Hillis-Steele, full-block barriers)
    for (int off = 1; off < NBIN; off <<= 1) {
        unsigned int u = 0;
        if (tid < NBIN && tid >= off) u = s_T[tid - off];
        __syncthreads();
        if (tid < NBIN && tid >= off) s_T[tid] += u;
        __syncthreads();
    }
    if (tid < NBIN) {
        unsigned int own = 0;
        #pragma unroll
        for (int w2 = 0; w2 < NW; w2++) own += s_cnt[w2 * NBIN + tid];
        unsigned int cs = s_T[tid] - own;            // exclusive CTA-local start
        s_cs[tid] = (unsigned short)cs;
        unsigned int run = cs;
        #pragma unroll
        for (int w2 = 0; w2 < NW; w2++) {
            s_ls[w2 * NBIN + tid] = (unsigned short)run;
            run += s_cnt[w2 * NBIN + tid];
        }
        s_db[tid] = g_binbase[tid] + g_warpoff[(size_t)tid * ngw + gw0];
    }
    __syncthreads();

    // stage: slot = ls[w][bid] + rank  (CTA-bin-major order)
    const unsigned short* ls = s_ls + w * NBIN;
    size_t segbase = (size_t)(gw0 + w) * SEG;
    #pragma unroll
    for (int r = 0; r < RND; r++) {
        size_t p = segbase + (size_t)r * 32 + lane;
        unsigned int pk = __ldcs(g_rank + p);
        float v = __ldcs(g_val + p);
        int b = pk >> 10;
        unsigned int slot = (unsigned int)ls[b] + (pk & 1023u);
        s_val[slot] = v;
        s_bin[slot] = (unsigned short)b;
    }
    __syncthreads();

    // flush: consecutive slots -> consecutive global dests (runs of ~64)
    #pragma unroll
    for (int s0 = 0; s0 < PPC; s0 += CTA1) {
        int s = s0 + tid;
        int b = s_bin[s];
        unsigned int dest = s_db[b] + (unsigned int)(s - (int)s_cs[b]);
        __stcs(out + dest, s_val[s]);
    }
}

extern "C" void kernel_launch(void* const* d_in, const int* in_sizes, int n_in,
                              void* d_out, int out_size) {
    const float* xyz  = (const float*)d_in[0];
    const float* aabb = (const float*)d_in[1];
    const float* vol  = (const float*)d_in[2];
    const float* dmin = (const float*)d_in[3];
    const float* dmax = (const float*)d_in[4];
    float* out = (float*)d_out;

    int n   = in_sizes[0] / 3;      // 4,194,304
    int ngw = n / SEG;              // 8192 warps
    int ncta = ngw / NW;            // 1024 CTAs

    k_fused<<<ncta, CTA1>>>(xyz, aabb, vol, dmin, dmax, ngw);
    k_scan_gw<<<NBIN, 256>>>(ngw);
    k_perm<<<ncta, CTA1>>>(out, ngw);
}

// round 12
// speedup vs baseline: 1.1379x; 1.0002x over previous
#include <cuda_runtime.h>

// AlphaGridMask: stable counting-sort by block id + trilinear grid_sample.
// N = 4,194,304 pts, 64 blocks, volume 256^3 f32 viewed as [64][64][64][64].
//
// Pass 1 (fused): per point compute bid (bit-exact), stable intra-warp rank
// (match_any + per-warp smem counters), and the trilinear sample. Store value
// + (bid,rank) in original order (coalesced, STREAMING stores so the 64MB
// volume stays L2-resident). Counts stored in [b][gw] and [gw][b] layouts.
// Pass 2 (single kernel): per-bin exclusive scan across warps; the LAST CTA
// (atomic ticket) also scans the 64 bin totals into g_binbase.
// Pass 3: permutation with smem staging in CTA-bin-major order so the global
// flush is fully coalesced (dest runs of ~64 consecutive elements per bin).

#define NBIN  64
#define CTA1  256
#define NW    8            // warps per CTA
#define RND   16           // rounds per warp -> 512 points per warp
#define SEG   512
#define PPC   (NW * SEG)   // 4096 points per CTA
#define NGWMAX 8192

__device__ float          g_val[4194304];            // sampled value, orig order
__device__ unsigned short g_rank[4194304];           // (bid<<10)|rank, orig order
__device__ unsigned int   g_warpcnt[NBIN * NGWMAX];  // [b][gw] counts (scan input)
__device__ unsigned int   g_warpcnt2[NGWMAX * NBIN]; // [gw][b] counts (perm input)
__device__ unsigned int   g_warpoff[NBIN * NGWMAX];  // [b][gw] exclusive prefix
__device__ unsigned int   g_bintot[NBIN];
__device__ unsigned int   g_binbase[NBIN];
__device__ unsigned int   g_sem;                     // last-block ticket

// Bit-exact block id vs reference: IEEE sub, IEEE div, floor, clip to [0,3].
__device__ __forceinline__ int bid_of(float x, float y, float z,
                                      float a0x, float a0y, float a0z,
                                      float vx, float vy, float vz) {
    float qx = __fdiv_rn(x - a0x, vx);
    float qy = __fdiv_rn(y - a0y, vy);
    float qz = __fdiv_rn(z - a0z, vz);
    int ix = (int)floorf(qx);
    int iy = (int)floorf(qy);
    int iz = (int)floorf(qz);
    ix = min(max(ix, 0), 3);
    iy = min(max(iy, 0), 3);
    iz = min(max(iz, 0), 3);
    return (ix << 4) + (iy << 2) + iz;   // strides [16,4,1]
}

__device__ __forceinline__ float sel4(float4 V, int s) {
    return (s == 0) ? V.x : ((s == 1) ? V.y : ((s == 2) ? V.z : V.w));
}

// ---------------- Pass 1 (fused): bid + rank + trilinear sample --------------
__global__ void __launch_bounds__(CTA1) k_fused(const float* __restrict__ xyz,
                                                const float* __restrict__ aabb,
                                                const float* __restrict__ vol,
                                                const float* __restrict__ dmin,
                                                const float* __restrict__ dmax,
                                                int ngw) {
    __shared__ unsigned int cnt[NW * NBIN];
    __shared__ float s_bb[6];
    __shared__ float s_org[NBIN * 3];
    __shared__ float s_scl[NBIN * 3];
    int tid = threadIdx.x, w = tid >> 5, lane = tid & 31;
    cnt[tid] = 0;
    cnt[tid + 256] = 0;
    if (tid < 6) s_bb[tid] = aabb[tid];
    if (blockIdx.x == 0 && tid == 0) g_sem = 0;      // reset ticket each launch
    for (int i = tid; i < NBIN * 3; i += CTA1) {
        float dn = dmin[i];
        s_org[i] = dn;
        s_scl[i] = 63.0f / (dmax[i] - dn);   // f = (p-dmin)*63/(dmax-dmin)
    }
    __syncthreads();

    float a0x = s_bb[0], a0y = s_bb[1], a0z = s_bb[2];
    float vx = (s_bb[3] - a0x) * 0.25f;      // /4 exact
    float vy = (s_bb[4] - a0y) * 0.25f;
    float vz = (s_bb[5] - a0z) * 0.25f;

    int gw = blockIdx.x * NW + w;
    size_t segbase = (size_t)gw * SEG;
    unsigned int lmlt = (1u << lane) - 1u;
    unsigned int* mycnt = cnt + w * NBIN;

    #pragma unroll 4
    for (int r = 0; r < RND; r++) {
        size_t p = segbase + (size_t)r * 32 + lane;
        const float* q = xyz + p * 3;
        float x = __ldcs(q + 0), y = __ldcs(q + 1), z = __ldcs(q + 2);
        int bid = bid_of(x, y, z, a0x, a0y, a0z, vx, vy, vz);

        // ---- stable rank via match (serial chain overlaps gather latency) ----
        unsigned int mask = __match_any_sync(0xffffffffu, bid);
        int leader = __ffs(mask) - 1;
        unsigned int base = 0;
        if (lane == leader) base = mycnt[bid];
        base = __shfl_sync(0xffffffffu, base, leader);
        unsigned int rank = base + __popc(mask & lmlt);
        if (lane == leader) mycnt[bid] = base + __popc(mask);
        __stcs(g_rank + p, (unsigned short)(((unsigned)bid << 10) | rank));

        // ---- trilinear sample (independent work) ----
        int b3 = bid * 3;
        float fx = (x - s_org[b3 + 0]) * s_scl[b3 + 0];
        float fy = (y - s_org[b3 + 1]) * s_scl[b3 + 1];
        float fz = (z - s_org[b3 + 2]) * s_scl[b3 + 2];
        float x0f = floorf(fx), y0f = floorf(fy), z0f = floorf(fz);
        float wx = fx - x0f, wy = fy - y0f, wzt = fz - z0f;
        int x0 = (int)x0f, y0 = (int)y0f, z0 = (int)z0f;
        int x0c = min(max(x0, 0), 63), x1c = min(max(x0 + 1, 0), 63);
        int y0c = min(max(y0, 0), 63), y1c = min(max(y0 + 1, 0), 63);
        int z0c = min(max(z0, 0), 63), z1c = min(max(z0 + 1, 0), 63);

        const float* vb = vol + ((size_t)bid << 18);
        int zy00 = ((z0c << 6) + y0c) << 6;
        int zy01 = ((z0c << 6) + y1c) << 6;
        int zy10 = ((z1c << 6) + y0c) << 6;
        int zy11 = ((z1c << 6) + y1c) << 6;

        int xb = x0c & ~3;                   // 16B-aligned base covering x0
        int s  = x0c & 3;

        float4 V00 = __ldg((const float4*)(vb + zy00 + xb));
        float4 V01 = __ldg((const float4*)(vb + zy01 + xb));
        float4 V10 = __ldg((const float4*)(vb + zy10 + xb));
        float4 V11 = __ldg((const float4*)(vb + zy11 + xb));

        float v000 = sel4(V00, s), v010 = sel4(V01, s);
        float v100 = sel4(V10, s), v110 = sel4(V11, s);
        float v001, v011, v101, v111;
        if (s < 3) {
            v001 = sel4(V00, s + 1);
            v011 = sel4(V01, s + 1);
            v101 = sel4(V10, s + 1);
            v111 = sel4(V11, s + 1);
        } else {                             // x0c%4==3: neighbor in next float4
            v001 = __ldg(vb + zy00 + x1c);
            v011 = __ldg(vb + zy01 + x1c);
            v101 = __ldg(vb + zy10 + x1c);
            v111 = __ldg(vb + zy11 + x1c);
        }

        float omx = 1.0f - wx, omy = 1.0f - wy, omz = 1.0f - wzt;
        float res = omz * (omy * (omx * v000 + wx * v001) + wy * (omx * v010 + wx * v011))
                  + wzt * (omy * (omx * v100 + wx * v101) + wy * (omx * v110 + wx * v111));
        __stcs(g_val + p, res);
        __syncwarp();
    }

    // per-warp bin totals, both layouts (streaming stores)
    __stcs(g_warpcnt  + (size_t)lane * ngw + gw,        mycnt[lane]);
    __stcs(g_warpcnt  + (size_t)(lane + 32) * ngw + gw, mycnt[lane + 32]);
    __stcs(g_warpcnt2 + (size_t)gw * NBIN + lane,       mycnt[lane]);
    __stcs(g_warpcnt2 + (size_t)gw * NBIN + 32 + lane,  mycnt[lane + 32]);
}

// ------- Pass 2: per-bin scan across warps; last CTA scans bin totals -------
__global__ void __launch_bounds__(256) k_scan_gw(int ngw) {
    int b = blockIdx.x, tid = threadIdx.x;
    const unsigned int* row = g_warpcnt + (size_t)b * ngw;
    unsigned int* orow = g_warpoff + (size_t)b * ngw;
    int per = (ngw + 255) >> 8;
    int base = tid * per;
    unsigned int s = 0;
    for (int k = 0; k < per; k++) { int i = base + k; if (i < ngw) s += row[i]; }
    __shared__ unsigned int sh[256];
    sh[tid] = s;
    __syncthreads();
    #pragma unroll
    for (int off = 1; off < 256; off <<= 1) {
        unsigned int v = (tid >= off) ? sh[tid - off] : 0;
        __syncthreads();
        if (tid >= off) sh[tid] += v;
        __syncthreads();
    }
    unsigned int incl = sh[tid];
    if (tid == 255) g_bintot[b] = incl;
    unsigned int run = incl - s;
    for (int k = 0; k < per; k++) {
        int i = base + k;
        if (i < ngw) { unsigned int v = row[i]; orow[i] = run; run += v; }
    }

    // last CTA computes g_binbase from g_bintot
    __shared__ unsigned int isLast;
    __threadfence();
    if (tid == 0) isLast = (atomicAdd(&g_sem, 1u) == NBIN - 1) ? 1u : 0u;
    __syncthreads();
    if (isLast) {
        __shared__ unsigned int bt[NBIN];
        if (tid < NBIN) bt[tid] = g_bintot[tid];
        __syncthreads();
        for (int off = 1; off < NBIN; off <<= 1) {
            unsigned int u = 0;
            if (tid < NBIN && tid >= off) u = bt[tid - off];
            __syncthreads();
            if (tid < NBIN && tid >= off) bt[tid] += u;
            __syncthreads();
        }
        if (tid < NBIN) g_binbase[tid] = bt[tid] - g_bintot[tid];
    }
}

// -------- Pass 3: permutation with CTA-bin-major smem staging ---------------
__global__ void __launch_bounds__(CTA1) k_perm(float* __restrict__ out, int ngw) {
    __shared__ float          s_val[PPC];            // 16KB staged values
    __shared__ unsigned short s_bin[PPC];            // 8KB  bin per slot
    __shared__ unsigned short s_cnt[NW * NBIN];      // counts [w][b]
    __shared__ unsigned short s_ls[NW * NBIN];       // slot start per (warp,bin)
    __shared__ unsigned short s_cs[NBIN];            // CTA-local bin start
    __shared__ unsigned int   s_db[NBIN];            // global dest base per bin
    __shared__ unsigned int   s_T[NBIN];
    int tid = threadIdx.x, w = tid >> 5, lane = tid & 31;
    int gw0 = blockIdx.x * NW;

    // counts, coalesced from [gw][b] layout (s_cnt[w][b] == g_warpcnt2[gw0+w][b])
    for (int i = tid; i < NW * NBIN; i += CTA1)
        s_cnt[i] = (unsigned short)g_warpcnt2[(size_t)gw0 * NBIN + i];
    __syncthreads();

    if (tid < NBIN) {
        unsigned int t = 0;
        #pragma unroll
        for (int w2 = 0; w2 < NW; w2++) t += s_cnt[w2 * NBIN + tid];
        s_T[tid] = t;
    }
    __syncthreads();
    // inclusive scan of s_T over 64 bins (Hillis-Steele, full-block barriers)
    for (int off = 1; off < NBIN; off <<= 1) {
        unsigned int u = 0;
        if (tid < NBIN && tid >= off) u = s_T[tid - off];
        __syncthreads();
        if (tid < NBIN && tid >= off) s_T[tid] += u;
        __syncthreads();
    }
    if (tid < NBIN) {
        unsigned int own = 0;
        #pragma unroll
        for (int w2 = 0; w2 < NW; w2++) own += s_cnt[w2 * NBIN + tid];
        unsigned int cs = s_T[tid] - own;            // exclusive CTA-local start
        s_cs[tid] = (unsigned short)cs;
        unsigned int run = cs;
        #pragma unroll
        for (int w2 = 0; w2 < NW; w2++) {
            s_ls[w2 * NBIN + tid] = (unsigned short)run;
            run += s_cnt[w2 * NBIN + tid];
        }
        s_db[tid] = g_binbase[tid] + g_warpoff[(size_t)tid * ngw + gw0];
    }
    __syncthreads();

    // stage: slot = ls[w][bid] + rank  (CTA-bin-major order)
    const unsigned short* ls = s_ls + w * NBIN;
    size_t segbase = (size_t)(gw0 + w) * SEG;
    #pragma unroll
    for (int r = 0; r < RND; r++) {
        size_t p = segbase + (size_t)r * 32 + lane;
        unsigned int pk = __ldcs(g_rank + p);
        float v = __ldcs(g_val + p);
        int b = pk >> 10;
        unsigned int slot = (unsigned int)ls[b] + (pk & 1023u);
        s_val[slot] = v;
        s_bin[slot] = (unsigned short)b;
    }
    __syncthreads();

    // flush: consecutive slots -> consecutive global dests (runs of ~64)
    #pragma unroll
    for (int s0 = 0; s0 < PPC; s0 += CTA1) {
        int s = s0 + tid;
        int b = s_bin[s];
        unsigned int dest = s_db[b] + (unsigned int)(s - (int)s_cs[b]);
        __stcs(out + dest, s_val[s]);
    }
}

extern "C" void kernel_launch(void* const* d_in, const int* in_sizes, int n_in,
                              void* d_out, int out_size) {
    const float* xyz  = (const float*)d_in[0];
    const float* aabb = (const float*)d_in[1];
    const float* vol  = (const float*)d_in[2];
    const float* dmin = (const float*)d_in[3];
    const float* dmax = (const float*)d_in[4];
    float* out = (float*)d_out;

    int n   = in_sizes[0] / 3;      // 4,194,304
    int ngw = n / SEG;              // 8192 warps
    int ncta = ngw / NW;            // 1024 CTAs

    k_fused<<<ncta, CTA1>>>(xyz, aabb, vol, dmin, dmax, ngw);
    k_scan_gw<<<NBIN, 256>>>(ngw);
    k_perm<<<ncta, CTA1>>>(out, ngw);
}

// round 13
// speedup vs baseline: 1.2348x; 1.0851x over previous
#include <cuda_runtime.h>

// AlphaGridMask: stable counting-sort by block id + trilinear grid_sample.
// N = 4,194,304 pts, 64 blocks, volume 256^3 f32 viewed as [64][64][64][64].
//
// Pass 1 (fused): per point compute bid (bit-exact), stable intra-warp rank
// (match_any + per-warp smem counters), and the trilinear sample. Store
// {val, (bid<<10)|rank} as ONE uint2 in original order. Per-warp bin counts
// go to [gw][b] (for k_perm); per-CTA bin totals go to [b][cta] (for the scan
// — k_perm rebuilds warp-level offsets locally, so CTA granularity suffices).
// Pass 2: per-bin exclusive scan across CTAs (1024 entries/bin); the LAST CTA
// (atomic ticket) also scans the 64 bin totals into g_binbase.
// Pass 3: permutation with smem staging in CTA-bin-major order so the global
// flush is fully coalesced (dest runs of ~64 consecutive elements per bin).

#define NBIN  64
#define CTA1  256
#define NW    8            // warps per CTA
#define RND   16           // rounds per warp -> 512 points per warp
#define SEG   512
#define PPC   (NW * SEG)   // 4096 points per CTA
#define NCTA  1024
#define NGWMAX 8192

__device__ uint2          g_vr[4194304];             // {val_bits, pk} orig order
__device__ unsigned int   g_warpcnt2[NGWMAX * NBIN]; // [gw][b] counts (perm input)
__device__ unsigned int   g_ctacnt[NBIN * NCTA];     // [b][cta] totals (scan in)
__device__ unsigned int   g_ctaoff[NBIN * NCTA];     // [b][cta] exclusive prefix
__device__ unsigned int   g_bintot[NBIN];
__device__ unsigned int   g_binbase[NBIN];
__device__ unsigned int   g_sem;                     // last-block ticket

// Bit-exact block id vs reference: IEEE sub, IEEE div, floor, clip to [0,3].
__device__ __forceinline__ int bid_of(float x, float y, float z,
                                      float a0x, float a0y, float a0z,
                                      float vx, float vy, float vz) {
    float qx = __fdiv_rn(x - a0x, vx);
    float qy = __fdiv_rn(y - a0y, vy);
    float qz = __fdiv_rn(z - a0z, vz);
    int ix = (int)floorf(qx);
    int iy = (int)floorf(qy);
    int iz = (int)floorf(qz);
    ix = min(max(ix, 0), 3);
    iy = min(max(iy, 0), 3);
    iz = min(max(iz, 0), 3);
    return (ix << 4) + (iy << 2) + iz;   // strides [16,4,1]
}

__device__ __forceinline__ float sel4(float4 V, int s) {
    return (s == 0) ? V.x : ((s == 1) ? V.y : ((s == 2) ? V.z : V.w));
}

// ---------------- Pass 1 (fused): bid + rank + trilinear sample --------------
__global__ void __launch_bounds__(CTA1) k_fused(const float* __restrict__ xyz,
                                                const float* __restrict__ aabb,
                                                const float* __restrict__ vol,
                                                const float* __restrict__ dmin,
                                                const float* __restrict__ dmax,
                                                int ngw) {
    __shared__ unsigned int cnt[NW * NBIN];
    __shared__ float s_bb[6];
    __shared__ float s_org[NBIN * 3];
    __shared__ float s_scl[NBIN * 3];
    int tid = threadIdx.x, w = tid >> 5, lane = tid & 31;
    cnt[tid] = 0;
    cnt[tid + 256] = 0;
    if (tid < 6) s_bb[tid] = aabb[tid];
    if (blockIdx.x == 0 && tid == 0) g_sem = 0;      // reset ticket each launch
    for (int i = tid; i < NBIN * 3; i += CTA1) {
        float dn = dmin[i];
        s_org[i] = dn;
        s_scl[i] = 63.0f / (dmax[i] - dn);   // f = (p-dmin)*63/(dmax-dmin)
    }
    __syncthreads();

    float a0x = s_bb[0], a0y = s_bb[1], a0z = s_bb[2];
    float vx = (s_bb[3] - a0x) * 0.25f;      // /4 exact
    float vy = (s_bb[4] - a0y) * 0.25f;
    float vz = (s_bb[5] - a0z) * 0.25f;

    int gw = blockIdx.x * NW + w;
    size_t segbase = (size_t)gw * SEG;
    unsigned int lmlt = (1u << lane) - 1u;
    unsigned int* mycnt = cnt + w * NBIN;

    #pragma unroll 4
    for (int r = 0; r < RND; r++) {
        size_t p = segbase + (size_t)r * 32 + lane;
        const float* q = xyz + p * 3;
        float x = __ldcs(q + 0), y = __ldcs(q + 1), z = __ldcs(q + 2);
        int bid = bid_of(x, y, z, a0x, a0y, a0z, vx, vy, vz);

        // ---- stable rank via match (serial chain overlaps gather latency) ----
        unsigned int mask = __match_any_sync(0xffffffffu, bid);
        int leader = __ffs(mask) - 1;
        unsigned int base = 0;
        if (lane == leader) base = mycnt[bid];
        base = __shfl_sync(0xffffffffu, base, leader);
        unsigned int rank = base + __popc(mask & lmlt);
        if (lane == leader) mycnt[bid] = base + __popc(mask);
        unsigned int pk = ((unsigned)bid << 10) | rank;

        // ---- trilinear sample (independent work) ----
        int b3 = bid * 3;
        float fx = (x - s_org[b3 + 0]) * s_scl[b3 + 0];
        float fy = (y - s_org[b3 + 1]) * s_scl[b3 + 1];
        float fz = (z - s_org[b3 + 2]) * s_scl[b3 + 2];
        float x0f = floorf(fx), y0f = floorf(fy), z0f = floorf(fz);
        float wx = fx - x0f, wy = fy - y0f, wzt = fz - z0f;
        int x0 = (int)x0f, y0 = (int)y0f, z0 = (int)z0f;
        int x0c = min(max(x0, 0), 63), x1c = min(max(x0 + 1, 0), 63);
        int y0c = min(max(y0, 0), 63), y1c = min(max(y0 + 1, 0), 63);
        int z0c = min(max(z0, 0), 63), z1c = min(max(z0 + 1, 0), 63);

        const float* vb = vol + ((size_t)bid << 18);
        int zy00 = ((z0c << 6) + y0c) << 6;
        int zy01 = ((z0c << 6) + y1c) << 6;
        int zy10 = ((z1c << 6) + y0c) << 6;
        int zy11 = ((z1c << 6) + y1c) << 6;

        int xb = x0c & ~3;                   // 16B-aligned base covering x0
        int s  = x0c & 3;

        float4 V00 = __ldg((const float4*)(vb + zy00 + xb));
        float4 V01 = __ldg((const float4*)(vb + zy01 + xb));
        float4 V10 = __ldg((const float4*)(vb + zy10 + xb));
        float4 V11 = __ldg((const float4*)(vb + zy11 + xb));

        float v000 = sel4(V00, s), v010 = sel4(V01, s);
        float v100 = sel4(V10, s), v110 = sel4(V11, s);
        float v001, v011, v101, v111;
        if (s < 3) {
            v001 = sel4(V00, s + 1);
            v011 = sel4(V01, s + 1);
            v101 = sel4(V10, s + 1);
            v111 = sel4(V11, s + 1);
        } else {                             // x0c%4==3: neighbor in next float4
            v001 = __ldg(vb + zy00 + x1c);
            v011 = __ldg(vb + zy01 + x1c);
            v101 = __ldg(vb + zy10 + x1c);
            v111 = __ldg(vb + zy11 + x1c);
        }

        float omx = 1.0f - wx, omy = 1.0f - wy, omz = 1.0f - wzt;
        float res = omz * (omy * (omx * v000 + wx * v001) + wy * (omx * v010 + wx * v011))
                  + wzt * (omy * (omx * v100 + wx * v101) + wy * (omx * v110 + wx * v111));
        __stcs(g_vr + p, make_uint2(__float_as_uint(res), pk));
        __syncwarp();
    }

    // per-warp counts for k_perm ([gw][b], coalesced)
    __stcs(g_warpcnt2 + (size_t)gw * NBIN + lane,      mycnt[lane]);
    __stcs(g_warpcnt2 + (size_t)gw * NBIN + 32 + lane, mycnt[lane + 32]);

    // per-CTA totals for the scan ([b][cta])
    __syncthreads();
    if (tid < NBIN) {
        unsigned int t = 0;
        #pragma unroll
        for (int w2 = 0; w2 < NW; w2++) t += cnt[w2 * NBIN + tid];
        g_ctacnt[(size_t)tid * NCTA + blockIdx.x] = t;
    }
}

// ------- Pass 2: per-bin scan across CTAs; last CTA scans bin totals -------
__global__ void __launch_bounds__(256) k_scan(int ncta) {
    int b = blockIdx.x, tid = threadIdx.x;
    const unsigned int* row = g_ctacnt + (size_t)b * NCTA;
    unsigned int* orow = g_ctaoff + (size_t)b * NCTA;
    int per = (ncta + 255) >> 8;                 // 4 for ncta=1024
    int base = tid * per;
    unsigned int s = 0;
    for (int k = 0; k < per; k++) { int i = base + k; if (i < ncta) s += row[i]; }
    __shared__ unsigned int sh[256];
    sh[tid] = s;
    __syncthreads();
    #pragma unroll
    for (int off = 1; off < 256; off <<= 1) {
        unsigned int v = (tid >= off) ? sh[tid - off] : 0;
        __syncthreads();
        if (tid >= off) sh[tid] += v;
        __syncthreads();
    }
    unsigned int incl = sh[tid];
    if (tid == 255) g_bintot[b] = incl;
    unsigned int run = incl - s;
    for (int k = 0; k < per; k++) {
        int i = base + k;
        if (i < ncta) { unsigned int v = row[i]; orow[i] = run; run += v; }
    }

    // last CTA computes g_binbase from g_bintot
    __shared__ unsigned int isLast;
    __threadfence();
    if (tid == 0) isLast = (atomicAdd(&g_sem, 1u) == NBIN - 1) ? 1u : 0u;
    __syncthreads();
    if (isLast) {
        __shared__ unsigned int bt[NBIN];
        if (tid < NBIN) bt[tid] = g_bintot[tid];
        __syncthreads();
        for (int off = 1; off < NBIN; off <<= 1) {
            unsigned int u = 0;
            if (tid < NBIN && tid >= off) u = bt[tid - off];
            __syncthreads();
            if (tid < NBIN && tid >= off) bt[tid] += u;
            __syncthreads();
        }
        if (tid < NBIN) g_binbase[tid] = bt[tid] - g_bintot[tid];
    }
}

// -------- Pass 3: permutation with CTA-bin-major smem staging ---------------
__global__ void __launch_bounds__(CTA1) k_perm(float* __restrict__ out, int ngw) {
    __shared__ uint2          s_sv[PPC];             // 32KB {val_bits, bin}
    __shared__ unsigned short s_cnt[NW * NBIN];      // counts [w][b]
    __shared__ unsigned short s_ls[NW * NBIN];       // slot start per (warp,bin)
    __shared__ unsigned short s_cs[NBIN];            // CTA-local bin start
    __shared__ unsigned int   s_db[NBIN];            // global dest base per bin
    __shared__ unsigned int   s_T[NBIN];
    int tid = threadIdx.x, w = tid >> 5, lane = tid & 31;
    int cta = blockIdx.x;
    int gw0 = cta * NW;

    // counts, coalesced from [gw][b] layout (s_cnt[w][b] == g_warpcnt2[gw0+w][b])
    for (int i = tid; i < NW * NBIN; i += CTA1)
        s_cnt[i] = (unsigned short)g_warpcnt2[(size_t)gw0 * NBIN + i];
    __syncthreads();

    if (tid < NBIN) {
        unsigned int t = 0;
        #pragma unroll
        for (int w2 = 0; w2 < NW; w2++) t += s_cnt[w2 * NBIN + tid];
        s_T[tid] = t;
    }
    __syncthreads();
    // inclusive scan of s_T over 64 bins (Hillis-Steele, full-block barriers)
    for (int off = 1; off < NBIN; off <<= 1) {
        unsigned int u = 0;
        if (tid < NBIN && tid >= off) u = s_T[tid - off];
        __syncthreads();
        if (tid < NBIN && tid >= off) s_T[tid] += u;
        __syncthreads();
    }
    if (tid < NBIN) {
        unsigned int own = 0;
        #pragma unroll
        for (int w2 = 0; w2 < NW; w2++) own += s_cnt[w2 * NBIN + tid];
        unsigned int cs = s_T[tid] - own;            // exclusive CTA-local start
        s_cs[tid] = (unsigned short)cs;
        unsigned int run = cs;
        #pragma unroll
        for (int w2 = 0; w2 < NW; w2++) {
            s_ls[w2 * NBIN + tid] = (unsigned short)run;
            run += s_cnt[w2 * NBIN + tid];
        }
        s_db[tid] = g_binbase[tid] + g_ctaoff[(size_t)tid * NCTA + cta];
    }
    __syncthreads();

    // stage: slot = ls[w][bid] + rank  (CTA-bin-major order)
    const unsigned short* ls = s_ls + w * NBIN;
    size_t segbase = (size_t)(gw0 + w) * SEG;
    #pragma unroll
    for (int r = 0; r < RND; r++) {
        size_t p = segbase + (size_t)r * 32 + lane;
        uint2 e = __ldcs(g_vr + p);
        int b = e.y >> 10;
        unsigned int slot = (unsigned int)ls[b] + (e.y & 1023u);
        s_sv[slot] = make_uint2(e.x, (unsigned int)b);
    }
    __syncthreads();

    // flush: consecutive slots -> consecutive global dests (runs of ~64)
    #pragma unroll
    for (int s0 = 0; s0 < PPC; s0 += CTA1) {
        int s = s0 + tid;
        uint2 e = s_sv[s];
        int b = (int)e.y;
        unsigned int dest = s_db[b] + (unsigned int)(s - (int)s_cs[b]);
        __stcs(out + dest, __uint_as_float(e.x));
    }
}

extern "C" void kernel_launch(void* const* d_in, const int* in_sizes, int n_in,
                              void* d_out, int out_size) {
    const float* xyz  = (const float*)d_in[0];
    const float* aabb = (const float*)d_in[1];
    const float* vol  = (const float*)d_in[2];
    const float* dmin = (const float*)d_in[3];
    const float* dmax = (const float*)d_in[4];
    float* out = (float*)d_out;

    int n   = in_sizes[0] / 3;      // 4,194,304
    int ngw = n / SEG;              // 8192 warps
    int ncta = ngw / NW;            // 1024 CTAs

    k_fused<<<ncta, CTA1>>>(xyz, aabb, vol, dmin, dmax, ngw);
    k_scan<<<NBIN, 256>>>(ncta);
    k_perm<<<ncta, CTA1>>>(out, ngw);
}

// round 14
// speedup vs baseline: 1.2599x; 1.0204x over previous
#include <cuda_runtime.h>

// AlphaGridMask: stable counting-sort by block id + trilinear grid_sample.
// N = 4,194,304 pts, 64 blocks, volume 256^3 f32 viewed as [64][64][64][64].
//
// Pass 1 (fused, phase-split): chunks of 8 points per thread.
//   Phase A: xyz load + bid + 4 float4 gathers + interp  (NO syncwarp, NO smem
//            writes -> maximal L1tex wavefront interleaving across rounds).
//   Phase B: stable intra-warp rank via match_any + per-warp smem counters
//            (serial chain + __syncwarp confined here), store {val,pk} uint2.
// Per-warp bin counts -> [gw][b] (k_perm preamble); per-CTA totals -> [b][cta].
// Pass 2: per-bin exclusive scan across CTAs; LAST CTA (atomic ticket) also
// scans the 64 bin totals into g_binbase.
// Pass 3: permutation with smem staging in CTA-bin-major order so the global
// flush is fully coalesced (dest runs of ~64 consecutive elements per bin).

#define NBIN  64
#define CTA1  256
#define NW    8            // warps per CTA
#define RND   16           // rounds per warp -> 512 points per warp
#define CHK   8            // rounds per phase-chunk
#define SEG   512
#define PPC   (NW * SEG)   // 4096 points per CTA
#define NCTA  1024
#define NGWMAX 8192

__device__ uint2          g_vr[4194304];             // {val_bits, pk} orig order
__device__ unsigned int   g_warpcnt2[NGWMAX * NBIN]; // [gw][b] counts (perm input)
__device__ unsigned int   g_ctacnt[NBIN * NCTA];     // [b][cta] totals (scan in)
__device__ unsigned int   g_ctaoff[NBIN * NCTA];     // [b][cta] exclusive prefix
__device__ unsigned int   g_bintot[NBIN];
__device__ unsigned int   g_binbase[NBIN];
__device__ unsigned int   g_sem;                     // last-block ticket

// Bit-exact block id vs reference: IEEE sub, IEEE div, floor, clip to [0,3].
__device__ __forceinline__ int bid_of(float x, float y, float z,
                                      float a0x, float a0y, float a0z,
                                      float vx, float vy, float vz) {
    float qx = __fdiv_rn(x - a0x, vx);
    float qy = __fdiv_rn(y - a0y, vy);
    float qz = __fdiv_rn(z - a0z, vz);
    int ix = (int)floorf(qx);
    int iy = (int)floorf(qy);
    int iz = (int)floorf(qz);
    ix = min(max(ix, 0), 3);
    iy = min(max(iy, 0), 3);
    iz = min(max(iz, 0), 3);
    return (ix << 4) + (iy << 2) + iz;   // strides [16,4,1]
}

__device__ __forceinline__ float sel4(float4 V, int s) {
    return (s == 0) ? V.x : ((s == 1) ? V.y : ((s == 2) ? V.z : V.w));
}

// ---------------- Pass 1 (fused): bid + rank + trilinear sample --------------
__global__ void __launch_bounds__(CTA1) k_fused(const float* __restrict__ xyz,
                                                const float* __restrict__ aabb,
                                                const float* __restrict__ vol,
                                                const float* __restrict__ dmin,
                                                const float* __restrict__ dmax,
                                                int ngw) {
    __shared__ unsigned int cnt[NW * NBIN];
    __shared__ float s_bb[6];
    __shared__ float s_org[NBIN * 3];
    __shared__ float s_scl[NBIN * 3];
    int tid = threadIdx.x, w = tid >> 5, lane = tid & 31;
    cnt[tid] = 0;
    cnt[tid + 256] = 0;
    if (tid < 6) s_bb[tid] = aabb[tid];
    if (blockIdx.x == 0 && tid == 0) g_sem = 0;      // reset ticket each launch
    for (int i = tid; i < NBIN * 3; i += CTA1) {
        float dn = dmin[i];
        s_org[i] = dn;
        s_scl[i] = 63.0f / (dmax[i] - dn);   // f = (p-dmin)*63/(dmax-dmin)
    }
    __syncthreads();

    float a0x = s_bb[0], a0y = s_bb[1], a0z = s_bb[2];
    float vx = (s_bb[3] - a0x) * 0.25f;      // /4 exact
    float vy = (s_bb[4] - a0y) * 0.25f;
    float vz = (s_bb[5] - a0z) * 0.25f;

    int gw = blockIdx.x * NW + w;
    size_t segbase = (size_t)gw * SEG;
    unsigned int lmlt = (1u << lane) - 1u;
    unsigned int* mycnt = cnt + w * NBIN;

    for (int c = 0; c < RND / CHK; c++) {
        float res[CHK];
        int   bids[CHK];

        // ---- Phase A: pure memory + math (independent rounds, max MLP) ----
        #pragma unroll
        for (int j = 0; j < CHK; j++) {
            size_t p = segbase + (size_t)(c * CHK + j) * 32 + lane;
            const float* q = xyz + p * 3;
            float x = __ldcs(q + 0), y = __ldcs(q + 1), z = __ldcs(q + 2);
            int bid = bid_of(x, y, z, a0x, a0y, a0z, vx, vy, vz);
            bids[j] = bid;

            int b3 = bid * 3;
            float fx = (x - s_org[b3 + 0]) * s_scl[b3 + 0];
            float fy = (y - s_org[b3 + 1]) * s_scl[b3 + 1];
            float fz = (z - s_org[b3 + 2]) * s_scl[b3 + 2];
            float x0f = floorf(fx), y0f = floorf(fy), z0f = floorf(fz);
            float wx = fx - x0f, wy = fy - y0f, wzt = fz - z0f;
            int x0 = (int)x0f, y0 = (int)y0f, z0 = (int)z0f;
            int x0c = min(max(x0, 0), 63), x1c = min(max(x0 + 1, 0), 63);
            int y0c = min(max(y0, 0), 63), y1c = min(max(y0 + 1, 0), 63);
            int z0c = min(max(z0, 0), 63), z1c = min(max(z0 + 1, 0), 63);

            const float* vb = vol + ((size_t)bid << 18);
            int zy00 = ((z0c << 6) + y0c) << 6;
            int zy01 = ((z0c << 6) + y1c) << 6;
            int zy10 = ((z1c << 6) + y0c) << 6;
            int zy11 = ((z1c << 6) + y1c) << 6;

            int xb = x0c & ~3;               // 16B-aligned base covering x0
            int s  = x0c & 3;

            float4 V00 = __ldg((const float4*)(vb + zy00 + xb));
            float4 V01 = __ldg((const float4*)(vb + zy01 + xb));
            float4 V10 = __ldg((const float4*)(vb + zy10 + xb));
            float4 V11 = __ldg((const float4*)(vb + zy11 + xb));

            float v000 = sel4(V00, s), v010 = sel4(V01, s);
            float v100 = sel4(V10, s), v110 = sel4(V11, s);
            float v001, v011, v101, v111;
            if (s < 3) {
                v001 = sel4(V00, s + 1);
                v011 = sel4(V01, s + 1);
                v101 = sel4(V10, s + 1);
                v111 = sel4(V11, s + 1);
            } else {                         // x0c%4==3: neighbor in next float4
                v001 = __ldg(vb + zy00 + x1c);
                v011 = __ldg(vb + zy01 + x1c);
                v101 = __ldg(vb + zy10 + x1c);
                v111 = __ldg(vb + zy11 + x1c);
            }

            float omx = 1.0f - wx, omy = 1.0f - wy, omz = 1.0f - wzt;
            res[j] = omz * (omy * (omx * v000 + wx * v001) + wy * (omx * v010 + wx * v011))
                   + wzt * (omy * (omx * v100 + wx * v101) + wy * (omx * v110 + wx * v111));
        }

        // ---- Phase B: stable rank chain (serial, syncwarp confined here) ----
        #pragma unroll
        for (int j = 0; j < CHK; j++) {
            int bid = bids[j];
            unsigned int mask = __match_any_sync(0xffffffffu, bid);
            int leader = __ffs(mask) - 1;
            unsigned int base = 0;
            if (lane == leader) base = mycnt[bid];
            base = __shfl_sync(0xffffffffu, base, leader);
            unsigned int rank = base + __popc(mask & lmlt);
            if (lane == leader) mycnt[bid] = base + __popc(mask);
            unsigned int pk = ((unsigned)bid << 10) | rank;
            size_t p = segbase + (size_t)(c * CHK + j) * 32 + lane;
            __stcs(g_vr + p, make_uint2(__float_as_uint(res[j]), pk));
            __syncwarp();
        }
    }

    // per-warp counts for k_perm ([gw][b], coalesced)
    __stcs(g_warpcnt2 + (size_t)gw * NBIN + lane,      mycnt[lane]);
    __stcs(g_warpcnt2 + (size_t)gw * NBIN + 32 + lane, mycnt[lane + 32]);

    // per-CTA totals for the scan ([b][cta])
    __syncthreads();
    if (tid < NBIN) {
        unsigned int t = 0;
        #pragma unroll
        for (int w2 = 0; w2 < NW; w2++) t += cnt[w2 * NBIN + tid];
        g_ctacnt[(size_t)tid * NCTA + blockIdx.x] = t;
    }
}

// ------- Pass 2: per-bin scan across CTAs; last CTA scans bin totals -------
__global__ void __launch_bounds__(256) k_scan(int ncta) {
    int b = blockIdx.x, tid = threadIdx.x;
    const unsigned int* row = g_ctacnt + (size_t)b * NCTA;
    unsigned int* orow = g_ctaoff + (size_t)b * NCTA;
    int per = (ncta + 255) >> 8;                 // 4 for ncta=1024
    int base = tid * per;
    unsigned int s = 0;
    for (int k = 0; k < per; k++) { int i = base + k; if (i < ncta) s += row[i]; }
    __shared__ unsigned int sh[256];
    sh[tid] = s;
    __syncthreads();
    #pragma unroll
    for (int off = 1; off < 256; off <<= 1) {
        unsigned int v = (tid >= off) ? sh[tid - off] : 0;
        __syncthreads();
        if (tid >= off) sh[tid] += v;
        __syncthreads();
    }
    unsigned int incl = sh[tid];
    if (tid == 255) g_bintot[b] = incl;
    unsigned int run = incl - s;
    for (int k = 0; k < per; k++) {
        int i = base + k;
        if (i < ncta) { unsigned int v = row[i]; orow[i] = run; run += v; }
    }

    // last CTA computes g_binbase from g_bintot
    __shared__ unsigned int isLast;
    __threadfence();
    if (tid == 0) isLast = (atomicAdd(&g_sem, 1u) == NBIN - 1) ? 1u : 0u;
    __syncthreads();
    if (isLast) {
        __shared__ unsigned int bt[NBIN];
        if (tid < NBIN) bt[tid] = g_bintot[tid];
        __syncthreads();
        for (int off = 1; off < NBIN; off <<= 1) {
            unsigned int u = 0;
            if (tid < NBIN && tid >= off) u = bt[tid - off];
            __syncthreads();
            if (tid < NBIN && tid >= off) bt[tid] += u;
            __syncthreads();
        }
        if (tid < NBIN) g_binbase[tid] = bt[tid] - g_bintot[tid];
    }
}

// -------- Pass 3: permutation with CTA-bin-major smem staging ---------------
__global__ void __launch_bounds__(CTA1) k_perm(float* __restrict__ out, int ngw) {
    __shared__ uint2          s_sv[PPC];             // 32KB {val_bits, bin}
    __shared__ unsigned short s_cnt[NW * NBIN];      // counts [w][b]
    __shared__ unsigned short s_ls[NW * NBIN];       // slot start per (warp,bin)
    __shared__ unsigned short s_cs[NBIN];            // CTA-local bin start
    __shared__ unsigned int   s_db[NBIN];            // global dest base per bin
    __shared__ unsigned int   s_T[NBIN];
    int tid = threadIdx.x, w = tid >> 5, lane = tid & 31;
    int cta = blockIdx.x;
    int gw0 = cta * NW;

    // counts, coalesced from [gw][b] layout (s_cnt[w][b] == g_warpcnt2[gw0+w][b])
    for (int i = tid; i < NW * NBIN; i += CTA1)
        s_cnt[i] = (unsigned short)g_warpcnt2[(size_t)gw0 * NBIN + i];
    __syncthreads();

    if (tid < NBIN) {
        unsigned int t = 0;
        #pragma unroll
        for (int w2 = 0; w2 < NW; w2++) t += s_cnt[w2 * NBIN + tid];
        s_T[tid] = t;
    }
    __syncthreads();
    // inclusive scan of s_T over 64 bins (Hillis-Steele, full-block barriers)
    for (int off = 1; off < NBIN; off <<= 1) {
        unsigned int u = 0;
        if (tid < NBIN && tid >= off) u = s_T[tid - off];
        __syncthreads();
        if (tid < NBIN && tid >= off) s_T[tid] += u;
        __syncthreads();
    }
    if (tid < NBIN) {
        unsigned int own = 0;
        #pragma unroll
        for (int w2 = 0; w2 < NW; w2++) own += s_cnt[w2 * NBIN + tid];
        unsigned int cs = s_T[tid] - own;            // exclusive CTA-local start
        s_cs[tid] = (unsigned short)cs;
        unsigned int run = cs;
        #pragma unroll
        for (int w2 = 0; w2 < NW; w2++) {
            s_ls[w2 * NBIN + tid] = (unsigned short)run;
            run += s_cnt[w2 * NBIN + tid];
        }
        s_db[tid] = g_binbase[tid] + g_ctaoff[(size_t)tid * NCTA + cta];
    }
    __syncthreads();

    // stage: slot = ls[w][bid] + rank  (CTA-bin-major order)
    const unsigned short* ls = s_ls + w * NBIN;
    size_t segbase = (size_t)(gw0 + w) * SEG;
    #pragma unroll
    for (int r = 0; r < RND; r++) {
        size_t p = segbase + (size_t)r * 32 + lane;
        uint2 e = __ldcs(g_vr + p);
        int b = e.y >> 10;
        unsigned int slot = (unsigned int)ls[b] + (e.y & 1023u);
        s_sv[slot] = make_uint2(e.x, (unsigned int)b);
    }
    __syncthreads();

    // flush: consecutive slots -> consecutive global dests (runs of ~64)
    #pragma unroll
    for (int s0 = 0; s0 < PPC; s0 += CTA1) {
        int s = s0 + tid;
        uint2 e = s_sv[s];
        int b = (int)e.y;
        unsigned int dest = s_db[b] + (unsigned int)(s - (int)s_cs[b]);
        __stcs(out + dest, __uint_as_float(e.x));
    }
}

extern "C" void kernel_launch(void* const* d_in, const int* in_sizes, int n_in,
                              void* d_out, int out_size) {
    const float* xyz  = (const float*)d_in[0];
    const float* aabb = (const float*)d_in[1];
    const float* vol  = (const float*)d_in[2];
    const float* dmin = (const float*)d_in[3];
    const float* dmax = (const float*)d_in[4];
    float* out = (float*)d_out;

    int n   = in_sizes[0] / 3;      // 4,194,304
    int ngw = n / SEG;              // 8192 warps
    int ncta = ngw / NW;            // 1024 CTAs

    k_fused<<<ncta, CTA1>>>(xyz, aabb, vol, dmin, dmax, ngw);
    k_scan<<<NBIN, 256>>>(ncta);
    k_perm<<<ncta, CTA1>>>(out, ngw);
}

// round 15
// speedup vs baseline: 1.3971x; 1.1089x over previous
#include <cuda_runtime.h>

// AlphaGridMask: stable counting-sort by block id + trilinear grid_sample.
// N = 4,194,304 pts, 64 blocks, volume 256^3 f32 viewed as [64][64][64][64].
//
// Pass 1 (fused, phase-split): chunks of 8 points per thread.
//   Phase A: xyz load + bid + 4 float4 gathers + interp  (no smem, max MLP).
//   Phase B: stable intra-warp rank via BALLOT-based match with REGISTER
//            counters (lane l owns bins l and l+32) -> no smem, no syncwarp;
//            serial chain is just shfl+add per round. Store {val,pk} uint2.
// Per-warp bin counts -> [gw][b] (k_perm preamble); per-CTA totals -> [b][cta].
// Pass 2: per-bin exclusive scan across CTAs; LAST CTA (atomic ticket) also
// scans the 64 bin totals into g_binbase.
// Pass 3: permutation with smem staging in CTA-bin-major order so the global
// flush is fully coalesced (dest runs of ~64 consecutive elements per bin).

#define NBIN  64
#define CTA1  256
#define NW    8            // warps per CTA
#define RND   16           // rounds per warp -> 512 points per warp
#define CHK   8            // rounds per phase-chunk
#define SEG   512
#define PPC   (NW * SEG)   // 4096 points per CTA
#define NCTA  1024
#define NGWMAX 8192

__device__ uint2          g_vr[4194304];             // {val_bits, pk} orig order
__device__ unsigned int   g_warpcnt2[NGWMAX * NBIN]; // [gw][b] counts (perm input)
__device__ unsigned int   g_ctacnt[NBIN * NCTA];     // [b][cta] totals (scan in)
__device__ unsigned int   g_ctaoff[NBIN * NCTA];     // [b][cta] exclusive prefix
__device__ unsigned int   g_bintot[NBIN];
__device__ unsigned int   g_binbase[NBIN];
__device__ unsigned int   g_sem;                     // last-block ticket

// Bit-exact block id vs reference: IEEE sub, IEEE div, floor, clip to [0,3].
__device__ __forceinline__ int bid_of(float x, float y, float z,
                                      float a0x, float a0y, float a0z,
                                      float vx, float vy, float vz) {
    float qx = __fdiv_rn(x - a0x, vx);
    float qy = __fdiv_rn(y - a0y, vy);
    float qz = __fdiv_rn(z - a0z, vz);
    int ix = (int)floorf(qx);
    int iy = (int)floorf(qy);
    int iz = (int)floorf(qz);
    ix = min(max(ix, 0), 3);
    iy = min(max(iy, 0), 3);
    iz = min(max(iz, 0), 3);
    return (ix << 4) + (iy << 2) + iz;   // strides [16,4,1]
}

__device__ __forceinline__ float sel4(float4 V, int s) {
    return (s == 0) ? V.x : ((s == 1) ? V.y : ((s == 2) ? V.z : V.w));
}

// ---------------- Pass 1 (fused): bid + rank + trilinear sample --------------
__global__ void __launch_bounds__(CTA1) k_fused(const float* __restrict__ xyz,
                                                const float* __restrict__ aabb,
                                                const float* __restrict__ vol,
                                                const float* __restrict__ dmin,
                                                const float* __restrict__ dmax,
                                                int ngw) {
    __shared__ unsigned int cnt[NW * NBIN];
    __shared__ float s_bb[6];
    __shared__ float s_org[NBIN * 3];
    __shared__ float s_scl[NBIN * 3];
    int tid = threadIdx.x, w = tid >> 5, lane = tid & 31;
    if (tid < 6) s_bb[tid] = aabb[tid];
    if (blockIdx.x == 0 && tid == 0) g_sem = 0;      // reset ticket each launch
    for (int i = tid; i < NBIN * 3; i += CTA1) {
        float dn = dmin[i];
        s_org[i] = dn;
        s_scl[i] = 63.0f / (dmax[i] - dn);   // f = (p-dmin)*63/(dmax-dmin)
    }
    __syncthreads();

    float a0x = s_bb[0], a0y = s_bb[1], a0z = s_bb[2];
    float vx = (s_bb[3] - a0x) * 0.25f;      // /4 exact
    float vy = (s_bb[4] - a0y) * 0.25f;
    float vz = (s_bb[5] - a0z) * 0.25f;

    int gw = blockIdx.x * NW + w;
    size_t segbase = (size_t)gw * SEG;
    unsigned int lmlt = (1u << lane) - 1u;
    unsigned int cnt_lo = 0;                 // counter for bin == lane
    unsigned int cnt_hi = 0;                 // counter for bin == lane+32

    for (int c = 0; c < RND / CHK; c++) {
        float res[CHK];
        int   bids[CHK];

        // ---- Phase A: pure memory + math (independent rounds, max MLP) ----
        #pragma unroll
        for (int j = 0; j < CHK; j++) {
            size_t p = segbase + (size_t)(c * CHK + j) * 32 + lane;
            const float* q = xyz + p * 3;
            float x = __ldcs(q + 0), y = __ldcs(q + 1), z = __ldcs(q + 2);
            int bid = bid_of(x, y, z, a0x, a0y, a0z, vx, vy, vz);
            bids[j] = bid;

            int b3 = bid * 3;
            float fx = (x - s_org[b3 + 0]) * s_scl[b3 + 0];
            float fy = (y - s_org[b3 + 1]) * s_scl[b3 + 1];
            float fz = (z - s_org[b3 + 2]) * s_scl[b3 + 2];
            float x0f = floorf(fx), y0f = floorf(fy), z0f = floorf(fz);
            float wx = fx - x0f, wy = fy - y0f, wzt = fz - z0f;
            int x0 = (int)x0f, y0 = (int)y0f, z0 = (int)z0f;
            int x0c = min(max(x0, 0), 63), x1c = min(max(x0 + 1, 0), 63);
            int y0c = min(max(y0, 0), 63), y1c = min(max(y0 + 1, 0), 63);
            int z0c = min(max(z0, 0), 63), z1c = min(max(z0 + 1, 0), 63);

            const float* vb = vol + ((size_t)bid << 18);
            int zy00 = ((z0c << 6) + y0c) << 6;
            int zy01 = ((z0c << 6) + y1c) << 6;
            int zy10 = ((z1c << 6) + y0c) << 6;
            int zy11 = ((z1c << 6) + y1c) << 6;

            int xb = x0c & ~3;               // 16B-aligned base covering x0
            int s  = x0c & 3;

            float4 V00 = __ldg((const float4*)(vb + zy00 + xb));
            float4 V01 = __ldg((const float4*)(vb + zy01 + xb));
            float4 V10 = __ldg((const float4*)(vb + zy10 + xb));
            float4 V11 = __ldg((const float4*)(vb + zy11 + xb));

            float v000 = sel4(V00, s), v010 = sel4(V01, s);
            float v100 = sel4(V10, s), v110 = sel4(V11, s);
            float v001, v011, v101, v111;
            if (s < 3) {
                v001 = sel4(V00, s + 1);
                v011 = sel4(V01, s + 1);
                v101 = sel4(V10, s + 1);
                v111 = sel4(V11, s + 1);
            } else {                         // x0c%4==3: neighbor in next float4
                v001 = __ldg(vb + zy00 + x1c);
                v011 = __ldg(vb + zy01 + x1c);
                v101 = __ldg(vb + zy10 + x1c);
                v111 = __ldg(vb + zy11 + x1c);
            }

            float omx = 1.0f - wx, omy = 1.0f - wy, omz = 1.0f - wzt;
            res[j] = omz * (omy * (omx * v000 + wx * v001) + wy * (omx * v010 + wx * v011))
                   + wzt * (omy * (omx * v100 + wx * v101) + wy * (omx * v110 + wx * v111));
        }

        // ---- Phase B: ballot-based stable ranks, register counters ----
        #pragma unroll
        for (int j = 0; j < CHK; j++) {
            int bid = bids[j];
            unsigned int B0 = __ballot_sync(0xffffffffu, bid & 1);
            unsigned int B1 = __ballot_sync(0xffffffffu, bid & 2);
            unsigned int B2 = __ballot_sync(0xffffffffu, bid & 4);
            unsigned int B3 = __ballot_sync(0xffffffffu, bid & 8);
            unsigned int B4 = __ballot_sync(0xffffffffu, bid & 16);
            unsigned int B5 = __ballot_sync(0xffffffffu, bid & 32);

            // my group mask (lanes with same bid)
            unsigned int m = ((bid & 1)  ? B0 : ~B0)
                           & ((bid & 2)  ? B1 : ~B1)
                           & ((bid & 4)  ? B2 : ~B2)
                           & ((bid & 8)  ? B3 : ~B3)
                           & ((bid & 16) ? B4 : ~B4)
                           & ((bid & 32) ? B5 : ~B5);

            // base = owner lane's current counter for my bin
            unsigned int lo = __shfl_sync(0xffffffffu, cnt_lo, bid & 31);
            unsigned int hi = __shfl_sync(0xffffffffu, cnt_hi, bid & 31);
            unsigned int base = (bid & 32) ? hi : lo;
            unsigned int rank = base + __popc(m & lmlt);

            // owner update for bins (lane) and (lane+32): first-5-bit mask
            unsigned int m5 = ((lane & 1)  ? B0 : ~B0)
                            & ((lane & 2)  ? B1 : ~B1)
                            & ((lane & 4)  ? B2 : ~B2)
                            & ((lane & 8)  ? B3 : ~B3)
                            & ((lane & 16) ? B4 : ~B4);
            cnt_lo += __popc(m5 & ~B5);
            cnt_hi += __popc(m5 &  B5);

            unsigned int pk = ((unsigned)bid << 10) | rank;
            size_t p = segbase + (size_t)(c * CHK + j) * 32 + lane;
            __stcs(g_vr + p, make_uint2(__float_as_uint(res[j]), pk));
        }
    }

    // per-warp counts for k_perm ([gw][b], coalesced)
    __stcs(g_warpcnt2 + (size_t)gw * NBIN + lane,      cnt_lo);
    __stcs(g_warpcnt2 + (size_t)gw * NBIN + 32 + lane, cnt_hi);

    // per-CTA totals for the scan ([b][cta])
    cnt[w * NBIN + lane]      = cnt_lo;
    cnt[w * NBIN + 32 + lane] = cnt_hi;
    __syncthreads();
    if (tid < NBIN) {
        unsigned int t = 0;
        #pragma unroll
        for (int w2 = 0; w2 < NW; w2++) t += cnt[w2 * NBIN + tid];
        g_ctacnt[(size_t)tid * NCTA + blockIdx.x] = t;
    }
}

// ------- Pass 2: per-bin scan across CTAs; last CTA scans bin totals -------
__global__ void __launch_bounds__(256) k_scan(int ncta) {
    int b = blockIdx.x, tid = threadIdx.x;
    const unsigned int* row = g_ctacnt + (size_t)b * NCTA;
    unsigned int* orow = g_ctaoff + (size_t)b * NCTA;
    int per = (ncta + 255) >> 8;                 // 4 for ncta=1024
    int base = tid * per;
    unsigned int s = 0;
    for (int k = 0; k < per; k++) { int i = base + k; if (i < ncta) s += row[i]; }
    __shared__ unsigned int sh[256];
    sh[tid] = s;
    __syncthreads();
    #pragma unroll
    for (int off = 1; off < 256; off <<= 1) {
        unsigned int v = (tid >= off) ? sh[tid - off] : 0;
        __syncthreads();
        if (tid >= off) sh[tid] += v;
        __syncthreads();
    }
    unsigned int incl = sh[tid];
    if (tid == 255) g_bintot[b] = incl;
    unsigned int run = incl - s;
    for (int k = 0; k < per; k++) {
        int i = base + k;
        if (i < ncta) { unsigned int v = row[i]; orow[i] = run; run += v; }
    }

    // last CTA computes g_binbase from g_bintot
    __shared__ unsigned int isLast;
    __threadfence();
    if (tid == 0) isLast = (atomicAdd(&g_sem, 1u) == NBIN - 1) ? 1u : 0u;
    __syncthreads();
    if (isLast) {
        __shared__ unsigned int bt[NBIN];
        if (tid < NBIN) bt[tid] = g_bintot[tid];
        __syncthreads();
        for (int off = 1; off < NBIN; off <<= 1) {
            unsigned int u = 0;
            if (tid < NBIN && tid >= off) u = bt[tid - off];
            __syncthreads();
            if (tid < NBIN && tid >= off) bt[tid] += u;
            __syncthreads();
        }
        if (tid < NBIN) g_binbase[tid] = bt[tid] - g_bintot[tid];
    }
}

// -------- Pass 3: permutation with CTA-bin-major smem staging ---------------
__global__ void __launch_bounds__(CTA1) k_perm(float* __restrict__ out, int ngw) {
    __shared__ uint2          s_sv[PPC];             // 32KB {val_bits, bin}
    __shared__ unsigned short s_cnt[NW * NBIN];      // counts [w][b]
    __shared__ unsigned short s_ls[NW * NBIN];       // slot start per (warp,bin)
    __shared__ unsigned short s_cs[NBIN];            // CTA-local bin start
    __shared__ unsigned int   s_db[NBIN];            // global dest base per bin
    __shared__ unsigned int   s_T[NBIN];
    int tid = threadIdx.x, w = tid >> 5, lane = tid & 31;
    int cta = blockIdx.x;
    int gw0 = cta * NW;

    // counts, coalesced from [gw][b] layout (s_cnt[w][b] == g_warpcnt2[gw0+w][b])
    for (int i = tid; i < NW * NBIN; i += CTA1)
        s_cnt[i] = (unsigned short)g_warpcnt2[(size_t)gw0 * NBIN + i];
    __syncthreads();

    if (tid < NBIN) {
        unsigned int t = 0;
        #pragma unroll
        for (int w2 = 0; w2 < NW; w2++) t += s_cnt[w2 * NBIN + tid];
        s_T[tid] = t;
    }
    __syncthreads();
    // inclusive scan of s_T over 64 bins (Hillis-Steele, full-block barriers)
    for (int off = 1; off < NBIN; off <<= 1) {
        unsigned int u = 0;
        if (tid < NBIN && tid >= off) u = s_T[tid - off];
        __syncthreads();
        if (tid < NBIN && tid >= off) s_T[tid] += u;
        __syncthreads();
    }
    if (tid < NBIN) {
        unsigned int own = 0;
        #pragma unroll
        for (int w2 = 0; w2 < NW; w2++) own += s_cnt[w2 * NBIN + tid];
        unsigned int cs = s_T[tid] - own;            // exclusive CTA-local start
        s_cs[tid] = (unsigned short)cs;
        unsigned int run = cs;
        #pragma unroll
        for (int w2 = 0; w2 < NW; w2++) {
            s_ls[w2 * NBIN + tid] = (unsigned short)run;
            run += s_cnt[w2 * NBIN + tid];
        }
        s_db[tid] = g_binbase[tid] + g_ctaoff[(size_t)tid * NCTA + cta];
    }
    __syncthreads();

    // stage: slot = ls[w][bid] + rank  (CTA-bin-major order)
    const unsigned short* ls = s_ls + w * NBIN;
    size_t segbase = (size_t)(gw0 + w) * SEG;
    #pragma unroll
    for (int r = 0; r < RND; r++) {
        size_t p = segbase + (size_t)r * 32 + lane;
        uint2 e = __ldcs(g_vr + p);
        int b = e.y >> 10;
        unsigned int slot = (unsigned int)ls[b] + (e.y & 1023u);
        s_sv[slot] = make_uint2(e.x, (unsigned int)b);
    }
    __syncthreads();

    // flush: consecutive slots -> consecutive global dests (runs of ~64)
    #pragma unroll
    for (int s0 = 0; s0 < PPC; s0 += CTA1) {
        int s = s0 + tid;
        uint2 e = s_sv[s];
        int b = (int)e.y;
        unsigned int dest = s_db[b] + (unsigned int)(s - (int)s_cs[b]);
        __stcs(out + dest, __uint_as_float(e.x));
    }
}

extern "C" void kernel_launch(void* const* d_in, const int* in_sizes, int n_in,
                              void* d_out, int out_size) {
    const float* xyz  = (const float*)d_in[0];
    const float* aabb = (const float*)d_in[1];
    const float* vol  = (const float*)d_in[2];
    const float* dmin = (const float*)d_in[3];
    const float* dmax = (const float*)d_in[4];
    float* out = (float*)d_out;

    int n   = in_sizes[0] / 3;      // 4,194,304
    int ngw = n / SEG;              // 8192 warps
    int ncta = ngw / NW;            // 1024 CTAs

    k_fused<<<ncta, CTA1>>>(xyz, aabb, vol, dmin, dmax, ngw);
    k_scan<<<NBIN, 256>>>(ncta);
    k_perm<<<ncta, CTA1>>>(out, ngw);
}